// round 5
// baseline (speedup 1.0000x reference)
#include <cuda_runtime.h>
#include <cuda_bf16.h>
#include <math.h>
#include <cstdint>

#define BB 8
#define NN 1025
#define CC 1024
#define HH 16
#define MM 25
#define TOT (BB*NN)           // 8200
#define QKVLD 3072
#define SCALE 0.125f

// ---------------- scratch (static device globals) ----------------
__device__ float g_qkv[TOT * QKVLD];
__device__ float g_router[BB * MM * CC];
__device__ float g_rlog[BB * HH * MM * NN];
__device__ float g_gate[BB * HH * MM * NN];
__device__ float g_av[BB * HH * MM * 64];
__device__ int   g_topk[BB * HH * MM * 25];
__device__ int   g_expert[BB * HH * NN];
__device__ float g_attn[TOT * CC];

// ================= PTX helpers =================
__device__ __forceinline__ uint32_t smem_u32(const void* p) {
    return (uint32_t)__cvta_generic_to_shared(p);
}
__device__ __forceinline__ void cp16(uint32_t saddr, const void* g) {
    asm volatile("cp.async.cg.shared.global [%0], [%1], 16;" :: "r"(saddr), "l"(g));
}
__device__ __forceinline__ void cp16z(uint32_t saddr, const void* g, bool ok) {
    int sz = ok ? 16 : 0;
    asm volatile("cp.async.cg.shared.global [%0], [%1], 16, %2;"
                 :: "r"(saddr), "l"(g), "r"(sz));
}

// ================= FP32 GEMM: 128x128x32, cp.async double-buffered =================
// As[2][128][36] (row-major, pad 4), Bs[2][32][128]. 256 threads, 8x8 per thread.
#define AS_STRIDE 36
#define AS_F (128*AS_STRIDE)   // 4608 floats per stage
#define BS_F (32*128)          // 4096 floats per stage
#define GEMM_SMEM ((2*AS_F + 2*BS_F) * 4)  // 69632 bytes

template<bool BIAS>
__global__ __launch_bounds__(256, 2) void fgemm(
    const float* __restrict__ A, const float* __restrict__ W,
    const float* __restrict__ bias, float* __restrict__ C,
    int M, int N, int K)
{
    extern __shared__ float sm[];
    float* AsBase = sm;                 // 2 stages
    float* BsBase = sm + 2*AS_F;
    const uint32_t sbA = smem_u32(AsBase);
    const uint32_t sbB = smem_u32(BsBase);

    const int tid = threadIdx.x;
    const int tx = tid & 15, ty = tid >> 4;
    const int m0 = blockIdx.y * 128, n0 = blockIdx.x * 128;

    // load maps (per stage: A 128x32 = 1024 float4, B 32x128 = 1024 float4)
    const int S = K >> 5;

    auto load_stage = [&](int kt, int buf) {
        const int k0 = kt * 32;
        const uint32_t dA = sbA + (uint32_t)buf * AS_F * 4;
        const uint32_t dB = sbB + (uint32_t)buf * BS_F * 4;
        #pragma unroll
        for (int i = 0; i < 4; i++) {
            int idx = i * 256 + tid;
            int ar = idx >> 3, ac = (idx & 7) * 4;
            cp16z(dA + (uint32_t)(ar*AS_STRIDE + ac)*4,
                  A + (size_t)(m0 + ar) * K + k0 + ac, (m0 + ar) < M);
        }
        #pragma unroll
        for (int i = 0; i < 4; i++) {
            int idx = i * 256 + tid;
            int wr = idx >> 5, wc = (idx & 31) * 4;
            cp16(dB + (uint32_t)(wr*128 + wc)*4,
                 W + (size_t)(k0 + wr) * N + n0 + wc);
        }
        asm volatile("cp.async.commit_group;" ::: "memory");
    };

    float acc[8][8];
    #pragma unroll
    for (int i = 0; i < 8; i++)
        #pragma unroll
        for (int j = 0; j < 8; j++) acc[i][j] = 0.0f;

    load_stage(0, 0);

    #pragma unroll 1
    for (int kt = 0; kt < S; kt++) {
        const int buf = kt & 1;
        if (kt + 1 < S) {
            load_stage(kt + 1, buf ^ 1);
            asm volatile("cp.async.wait_group 1;" ::: "memory");
        } else {
            asm volatile("cp.async.wait_group 0;" ::: "memory");
        }
        __syncthreads();

        const float* a   = AsBase + buf * AS_F;
        const float* bsm = BsBase + buf * BS_F;

        #pragma unroll
        for (int kk = 0; kk < 32; kk += 2) {
            float2 a2[8];
            #pragma unroll
            for (int i = 0; i < 8; i++) {
                int r = (i < 4) ? (ty*4 + i) : (64 + ty*4 + (i - 4));
                a2[i] = *(const float2*)&a[r*AS_STRIDE + kk];
            }
            float4 b00 = *(const float4*)&bsm[kk*128 + tx*4];
            float4 b01 = *(const float4*)&bsm[kk*128 + 64 + tx*4];
            float4 b10 = *(const float4*)&bsm[(kk+1)*128 + tx*4];
            float4 b11 = *(const float4*)&bsm[(kk+1)*128 + 64 + tx*4];
            float blo[8] = {b00.x, b00.y, b00.z, b00.w, b01.x, b01.y, b01.z, b01.w};
            float bhi[8] = {b10.x, b10.y, b10.z, b10.w, b11.x, b11.y, b11.z, b11.w};
            #pragma unroll
            for (int i = 0; i < 8; i++)
                #pragma unroll
                for (int j = 0; j < 8; j++)
                    acc[i][j] += a2[i].x * blo[j] + a2[i].y * bhi[j];
        }
        __syncthreads();
    }

    // epilogue
    #pragma unroll
    for (int i = 0; i < 8; i++) {
        int r = m0 + ((i < 4) ? (ty*4 + i) : (64 + ty*4 + (i - 4)));
        if (r >= M) continue;
        int c0 = n0 + tx*4;
        int c1 = n0 + 64 + tx*4;
        float4 o0, o1;
        o0.x = acc[i][0]; o0.y = acc[i][1]; o0.z = acc[i][2]; o0.w = acc[i][3];
        o1.x = acc[i][4]; o1.y = acc[i][5]; o1.z = acc[i][6]; o1.w = acc[i][7];
        if (BIAS) {
            float4 bv0 = *(const float4*)&bias[c0];
            float4 bv1 = *(const float4*)&bias[c1];
            o0.x += bv0.x; o0.y += bv0.y; o0.z += bv0.z; o0.w += bv0.w;
            o1.x += bv1.x; o1.y += bv1.y; o1.z += bv1.z; o1.w += bv1.w;
        }
        *(float4*)&C[(size_t)r * N + c0] = o0;
        *(float4*)&C[(size_t)r * N + c1] = o1;
    }
}

// ---------------- Router: adaptive avg pool of q (32x32 -> 5x5) ----------------
__global__ void router_kernel(const float* __restrict__ qkv, float* __restrict__ router) {
    const int m = blockIdx.x, b = blockIdx.y;
    const int i = m / 5, j = m % 5;
    const int s[5] = {0, 6, 12, 19, 25};
    const int e[5] = {7, 13, 20, 26, 32};
    const float inv = 1.0f / (float)((e[i]-s[i]) * (e[j]-s[j]));
    for (int c = threadIdx.x; c < CC; c += blockDim.x) {
        float acc = 0.0f;
        for (int gh = s[i]; gh < e[i]; gh++)
            for (int gw = s[j]; gw < e[j]; gw++)
                acc += qkv[(size_t)(b*NN + gh*32 + gw) * QKVLD + c];
        router[(size_t)(b*MM + m) * CC + c] = acc * inv;
    }
}

// ---------------- r_logits = r@k^T, gate = r@q^T ----------------
__global__ void rg_kernel(const float* __restrict__ qkv, const float* __restrict__ router,
                          float* __restrict__ rlog, float* __restrict__ gate) {
    const int bh = blockIdx.y;
    const int b = bh >> 4, h = bh & 15;
    const int t0 = blockIdx.x * 256;
    const int tid = threadIdx.x;
    __shared__ float rsm[25][64];
    __shared__ float ks[256][17];
    __shared__ float qs[256][17];

    for (int idx = tid; idx < 1600; idx += 256)
        rsm[idx >> 6][idx & 63] = router[(size_t)(b*MM + (idx >> 6)) * CC + h*64 + (idx & 63)];

    float acc_k[25], acc_q[25];
    #pragma unroll
    for (int m = 0; m < 25; m++) { acc_k[m] = 0.0f; acc_q[m] = 0.0f; }

    const int n = t0 + tid;
    for (int dc = 0; dc < 64; dc += 16) {
        __syncthreads();
        for (int idx = tid; idx < 256*16; idx += 256) {
            int tok = idx >> 4, dd = idx & 15;
            int gn = t0 + tok;
            float kv = 0.0f, qv = 0.0f;
            if (gn < NN) {
                const float* base = qkv + (size_t)(b*NN + gn) * QKVLD + h*64 + dc + dd;
                qv = base[0];
                kv = base[1024];
            }
            ks[tok][dd] = kv; qs[tok][dd] = qv;
        }
        __syncthreads();
        #pragma unroll
        for (int d = 0; d < 16; d++) {
            float kd = ks[tid][d], qd = qs[tid][d];
            #pragma unroll
            for (int m = 0; m < 25; m++) {
                float r = rsm[m][dc + d];
                acc_k[m] += r * kd;
                acc_q[m] += r * qd;
            }
        }
    }
    if (n < NN) {
        #pragma unroll
        for (int m = 0; m < 25; m++) {
            rlog[((size_t)bh*MM + m) * NN + n] = acc_k[m];
            gate[((size_t)bh*MM + m) * NN + n] = acc_q[m];
        }
    }
}

// ---------------- Agent branch: softmax(r_logits*scale) @ V ----------------
__global__ void agent_kernel(const float* __restrict__ rlog, const float* __restrict__ qkv,
                             float* __restrict__ av) {
    const int bhm = blockIdx.x;
    const int bh = bhm / 25;
    const int b = bh >> 4, h = bh & 15;
    const float* row = rlog + (size_t)bhm * NN;
    __shared__ float p[NN];
    __shared__ float red[256];
    __shared__ float part[4][64];
    const int tid = threadIdx.x;      // 256

    float mx = -INFINITY;
    for (int n = tid; n < NN; n += 256) mx = fmaxf(mx, row[n]);
    red[tid] = mx; __syncthreads();
    for (int s = 128; s > 0; s >>= 1) {
        if (tid < s) red[tid] = fmaxf(red[tid], red[tid + s]);
        __syncthreads();
    }
    mx = red[0];
    __syncthreads();

    float sum = 0.0f;
    for (int n = tid; n < NN; n += 256) {
        float e = __expf((row[n] - mx) * SCALE);
        p[n] = e; sum += e;
    }
    red[tid] = sum; __syncthreads();
    for (int s = 128; s > 0; s >>= 1) {
        if (tid < s) red[tid] += red[tid + s];
        __syncthreads();
    }
    const float inv = 1.0f / red[0];

    const int g = tid >> 6, d = tid & 63;
    const float* vb = qkv + (size_t)b*NN*QKVLD + 2048 + h*64 + d;
    float acc = 0.0f;
    #pragma unroll 8
    for (int n = g; n < NN; n += 4) acc += p[n] * vb[(size_t)n * QKVLD];
    part[g][d] = acc;
    __syncthreads();
    if (tid < 64)
        av[(size_t)bhm * 64 + tid] =
            (part[0][tid] + part[1][tid] + part[2][tid] + part[3][tid]) * inv;
}

// ---------------- Top-25 key indices per (bh,m) ----------------
__global__ void topk_kernel(const float* __restrict__ rlog, int* __restrict__ topk) {
    const int bhm = blockIdx.x;
    __shared__ float vals[NN];
    __shared__ float bmax[256];
    __shared__ int bidx[256];
    const int tid = threadIdx.x;
    for (int n = tid; n < NN; n += 256) vals[n] = rlog[(size_t)bhm * NN + n];
    __syncthreads();
    for (int it = 0; it < 25; it++) {
        float best = -INFINITY; int bi = NN;
        for (int n = tid; n < NN; n += 256) {
            float v = vals[n];
            if (v > best || (v == best && n < bi)) { best = v; bi = n; }
        }
        bmax[tid] = best; bidx[tid] = bi; __syncthreads();
        for (int s = 128; s > 0; s >>= 1) {
            if (tid < s) {
                if (bmax[tid+s] > bmax[tid] ||
                    (bmax[tid+s] == bmax[tid] && bidx[tid+s] < bidx[tid])) {
                    bmax[tid] = bmax[tid+s]; bidx[tid] = bidx[tid+s];
                }
            }
            __syncthreads();
        }
        if (tid == 0) {
            topk[bhm * 25 + it] = bidx[0];
            vals[bidx[0]] = -INFINITY;
        }
        __syncthreads();
    }
}

// ---------------- Per-query expert argmax ----------------
__global__ void expert_kernel(const float* __restrict__ gate, int* __restrict__ expert) {
    const int idx = blockIdx.x * 256 + threadIdx.x;
    if (idx >= BB*HH*NN) return;
    const int bh = idx / NN, n = idx % NN;
    const float* g = gate + (size_t)bh * MM * NN + n;
    float best = g[0]; int bi = 0;
    #pragma unroll
    for (int m = 1; m < 25; m++) {
        float v = g[(size_t)m * NN];
        if (v > best) { best = v; bi = m; }
    }
    expert[idx] = bi;
}

// ---------------- Mixed attention ----------------
__global__ void mixed_kernel(const float* __restrict__ qkv, const float* __restrict__ gate,
                             const float* __restrict__ av, const int* __restrict__ topk,
                             const int* __restrict__ expert, float* __restrict__ attn) {
    const int bh = blockIdx.y;
    const int b = bh >> 4, h = bh & 15;
    const int tid = threadIdx.x, lane = tid & 31, w = tid >> 5;
    __shared__ float avs[25][64];
    __shared__ float ws[8][50];
    for (int idx = tid; idx < 1600; idx += 256)
        avs[idx >> 6][idx & 63] = av[(size_t)bh * 1600 + idx];
    __syncthreads();

    const int n = blockIdx.x * 8 + w;
    if (n >= NN) return;

    const int e = expert[bh * NN + n];
    const int sel = (lane < 25) ? topk[((size_t)bh*MM + e) * 25 + lane] : 0;

    const float* qrow = qkv + (size_t)(b*NN + n) * QKVLD + h*64;
    const float qa = qrow[lane], qb = qrow[lane + 32];
    const float* kb = qkv + (size_t)b*NN*QKVLD + 1024 + h*64;
    const float* vb = qkv + (size_t)b*NN*QKVLD + 2048 + h*64;

    float L0 = -INFINITY, L1 = -INFINITY;
    if (lane < 25) L0 = gate[((size_t)bh*MM + lane) * NN + n] * SCALE;

    #pragma unroll
    for (int k = 0; k < 25; k++) {
        int s = __shfl_sync(0xffffffffu, sel, k);
        const float* kr = kb + (size_t)s * QKVLD;
        float part = qa * kr[lane] + qb * kr[lane + 32];
        #pragma unroll
        for (int o = 16; o > 0; o >>= 1) part += __shfl_xor_sync(0xffffffffu, part, o);
        part *= SCALE;
        const int j = 25 + k;
        if (j < 32) { if (lane == j) L0 = part; }
        else        { if (lane == j - 32) L1 = part; }
    }

    float mx = fmaxf(L0, L1);
    #pragma unroll
    for (int o = 16; o > 0; o >>= 1) mx = fmaxf(mx, __shfl_xor_sync(0xffffffffu, mx, o));
    float p0 = __expf(L0 - mx), p1 = __expf(L1 - mx);
    float ssum = p0 + p1;
    #pragma unroll
    for (int o = 16; o > 0; o >>= 1) ssum += __shfl_xor_sync(0xffffffffu, ssum, o);
    const float invs = 1.0f / ssum;

    ws[w][lane] = p0 * invs;
    if (lane < 18) ws[w][32 + lane] = p1 * invs;
    __syncwarp();

    float o0 = 0.0f, o1 = 0.0f;
    #pragma unroll
    for (int m = 0; m < 25; m++) {
        float wt = ws[w][m];
        o0 += wt * avs[m][lane];
        o1 += wt * avs[m][lane + 32];
    }
    #pragma unroll
    for (int k = 0; k < 25; k++) {
        float wt = ws[w][25 + k];
        int s = __shfl_sync(0xffffffffu, sel, k);
        const float* vr = vb + (size_t)s * QKVLD;
        o0 += wt * vr[lane];
        o1 += wt * vr[lane + 32];
    }
    attn[(size_t)(b*NN + n) * CC + h*64 + lane] = o0;
    attn[(size_t)(b*NN + n) * CC + h*64 + lane + 32] = o1;
}

// ---------------- launch ----------------
extern "C" void kernel_launch(void* const* d_in, const int* in_sizes, int n_in,
                              void* d_out, int out_size) {
    const float* x     = (const float*)d_in[0];   // [8,1025,1024]
    const float* Wqkv  = (const float*)d_in[1];   // [1024,3072]
    const float* Wproj = (const float*)d_in[2];   // [1024,1024]
    const float* bproj = (const float*)d_in[3];   // [1024]
    float* out = (float*)d_out;                   // [8,1025,1024]

    float *qkv_p, *router_p, *rlog_p, *gate_p, *av_p, *attn_p;
    int *topk_p, *expert_p;
    cudaGetSymbolAddress((void**)&qkv_p,    g_qkv);
    cudaGetSymbolAddress((void**)&router_p, g_router);
    cudaGetSymbolAddress((void**)&rlog_p,   g_rlog);
    cudaGetSymbolAddress((void**)&gate_p,   g_gate);
    cudaGetSymbolAddress((void**)&av_p,     g_av);
    cudaGetSymbolAddress((void**)&topk_p,   g_topk);
    cudaGetSymbolAddress((void**)&expert_p, g_expert);
    cudaGetSymbolAddress((void**)&attn_p,   g_attn);

    cudaFuncSetAttribute(fgemm<false>,
                         cudaFuncAttributeMaxDynamicSharedMemorySize, GEMM_SMEM);
    cudaFuncSetAttribute(fgemm<true>,
                         cudaFuncAttributeMaxDynamicSharedMemorySize, GEMM_SMEM);

    // 1) qkv = x @ Wqkv
    fgemm<false><<<dim3(QKVLD/128, (TOT+127)/128), 256, GEMM_SMEM>>>(
        x, Wqkv, nullptr, qkv_p, TOT, QKVLD, CC);

    // 2) router tokens
    router_kernel<<<dim3(MM, BB), 256>>>(qkv_p, router_p);

    // 3) r_logits and gate
    rg_kernel<<<dim3((NN+255)/256, BB*HH), 256>>>(qkv_p, router_p, rlog_p, gate_p);

    // 4) agent values
    agent_kernel<<<BB*HH*MM, 256>>>(rlog_p, qkv_p, av_p);

    // 5) top-25 keys per expert
    topk_kernel<<<BB*HH*MM, 256>>>(rlog_p, topk_p);

    // 6) per-query expert
    expert_kernel<<<(BB*HH*NN + 255)/256, 256>>>(gate_p, expert_p);

    // 7) mixed attention
    mixed_kernel<<<dim3((NN+7)/8, BB*HH), 256>>>(qkv_p, gate_p, av_p, topk_p, expert_p, attn_p);

    // 8) out = attn @ Wproj + bproj
    fgemm<true><<<dim3(CC/128, (TOT+127)/128), 256, GEMM_SMEM>>>(
        attn_p, Wproj, bproj, out, TOT, CC, CC);
}

// round 6
// speedup vs baseline: 1.0654x; 1.0654x over previous
#include <cuda_runtime.h>
#include <cuda_bf16.h>
#include <math.h>
#include <cstdint>

#define BB 8
#define NN 1025
#define CC 1024
#define HH 16
#define MM 25
#define TOT (BB*NN)           // 8200
#define QKVLD 3072
#define SCALE 0.125f

// ---------------- scratch (static device globals) ----------------
__device__ float g_qkv[TOT * QKVLD];
__device__ float g_router[BB * MM * CC];
__device__ float g_rlog[BB * HH * MM * NN];
__device__ float g_gate[BB * HH * MM * NN];
__device__ float g_av[BB * HH * MM * 64];
__device__ int   g_topk[BB * HH * MM * 25];
__device__ int   g_expert[BB * HH * NN];
__device__ float g_attn[TOT * CC];

// ================= PTX helpers =================
__device__ __forceinline__ uint32_t smem_u32(const void* p) {
    return (uint32_t)__cvta_generic_to_shared(p);
}
__device__ __forceinline__ void cp16(uint32_t saddr, const void* g) {
    asm volatile("cp.async.cg.shared.global [%0], [%1], 16;" :: "r"(saddr), "l"(g));
}
__device__ __forceinline__ void cp16z(uint32_t saddr, const void* g, bool ok) {
    int sz = ok ? 16 : 0;
    asm volatile("cp.async.cg.shared.global [%0], [%1], 16, %2;"
                 :: "r"(saddr), "l"(g), "r"(sz));
}
__device__ __forceinline__ uint32_t f2tf(float v) {
    uint32_t r; asm("cvt.rna.tf32.f32 %0, %1;" : "=r"(r) : "f"(v)); return r;
}
__device__ __forceinline__ void split_tf(float v, uint32_t& hi, uint32_t& lo) {
    hi = f2tf(v);
    lo = f2tf(v - __uint_as_float(hi));
}
__device__ __forceinline__ void mma_tf32(float* c, const uint32_t* a, uint32_t b0, uint32_t b1) {
    asm volatile("mma.sync.aligned.m16n8k8.row.col.f32.tf32.tf32.f32 "
        "{%0,%1,%2,%3}, {%4,%5,%6,%7}, {%8,%9}, {%0,%1,%2,%3};"
        : "+f"(c[0]), "+f"(c[1]), "+f"(c[2]), "+f"(c[3])
        : "r"(a[0]), "r"(a[1]), "r"(a[2]), "r"(a[3]), "r"(b0), "r"(b1));
}

// ================= FP32 GEMM (GEMM1): 128x128x32, cp.async double-buffered =================
#define AS_STRIDE 36
#define AS_F (128*AS_STRIDE)   // 4608 floats per stage
#define BS_F (32*128)          // 4096 floats per stage
#define GEMM_SMEM ((2*AS_F + 2*BS_F) * 4)  // 69632 bytes

__global__ __launch_bounds__(256) void fgemm(
    const float* __restrict__ A, const float* __restrict__ W,
    float* __restrict__ C, int M, int N, int K)
{
    extern __shared__ float sm[];
    float* AsBase = sm;
    float* BsBase = sm + 2*AS_F;
    const uint32_t sbA = smem_u32(AsBase);
    const uint32_t sbB = smem_u32(BsBase);

    const int tid = threadIdx.x;
    const int tx = tid & 15, ty = tid >> 4;
    const int m0 = blockIdx.y * 128, n0 = blockIdx.x * 128;

    const int S = K >> 5;

    auto load_stage = [&](int kt, int buf) {
        const int k0 = kt * 32;
        const uint32_t dA = sbA + (uint32_t)buf * AS_F * 4;
        const uint32_t dB = sbB + (uint32_t)buf * BS_F * 4;
        #pragma unroll
        for (int i = 0; i < 4; i++) {
            int idx = i * 256 + tid;
            int ar = idx >> 3, ac = (idx & 7) * 4;
            cp16z(dA + (uint32_t)(ar*AS_STRIDE + ac)*4,
                  A + (size_t)(m0 + ar) * K + k0 + ac, (m0 + ar) < M);
        }
        #pragma unroll
        for (int i = 0; i < 4; i++) {
            int idx = i * 256 + tid;
            int wr = idx >> 5, wc = (idx & 31) * 4;
            cp16(dB + (uint32_t)(wr*128 + wc)*4,
                 W + (size_t)(k0 + wr) * N + n0 + wc);
        }
        asm volatile("cp.async.commit_group;" ::: "memory");
    };

    float acc[8][8];
    #pragma unroll
    for (int i = 0; i < 8; i++)
        #pragma unroll
        for (int j = 0; j < 8; j++) acc[i][j] = 0.0f;

    load_stage(0, 0);

    #pragma unroll 1
    for (int kt = 0; kt < S; kt++) {
        const int buf = kt & 1;
        if (kt + 1 < S) {
            load_stage(kt + 1, buf ^ 1);
            asm volatile("cp.async.wait_group 1;" ::: "memory");
        } else {
            asm volatile("cp.async.wait_group 0;" ::: "memory");
        }
        __syncthreads();

        const float* a   = AsBase + buf * AS_F;
        const float* bsm = BsBase + buf * BS_F;

        #pragma unroll
        for (int kk = 0; kk < 32; kk += 2) {
            float2 a2[8];
            #pragma unroll
            for (int i = 0; i < 8; i++) {
                int r = (i < 4) ? (ty*4 + i) : (64 + ty*4 + (i - 4));
                a2[i] = *(const float2*)&a[r*AS_STRIDE + kk];
            }
            float4 b00 = *(const float4*)&bsm[kk*128 + tx*4];
            float4 b01 = *(const float4*)&bsm[kk*128 + 64 + tx*4];
            float4 b10 = *(const float4*)&bsm[(kk+1)*128 + tx*4];
            float4 b11 = *(const float4*)&bsm[(kk+1)*128 + 64 + tx*4];
            float blo[8] = {b00.x, b00.y, b00.z, b00.w, b01.x, b01.y, b01.z, b01.w};
            float bhi[8] = {b10.x, b10.y, b10.z, b10.w, b11.x, b11.y, b11.z, b11.w};
            #pragma unroll
            for (int i = 0; i < 8; i++)
                #pragma unroll
                for (int j = 0; j < 8; j++)
                    acc[i][j] += a2[i].x * blo[j] + a2[i].y * bhi[j];
        }
        __syncthreads();
    }

    #pragma unroll
    for (int i = 0; i < 8; i++) {
        int r = m0 + ((i < 4) ? (ty*4 + i) : (64 + ty*4 + (i - 4)));
        if (r >= M) continue;
        int c0 = n0 + tx*4;
        int c1 = n0 + 64 + tx*4;
        float4 o0, o1;
        o0.x = acc[i][0]; o0.y = acc[i][1]; o0.z = acc[i][2]; o0.w = acc[i][3];
        o1.x = acc[i][4]; o1.y = acc[i][5]; o1.z = acc[i][6]; o1.w = acc[i][7];
        *(float4*)&C[(size_t)r * N + c0] = o0;
        *(float4*)&C[(size_t)r * N + c1] = o1;
    }
}

// ================= 3xTF32 GEMM (GEMM2 only — flip-immune, feeds final output) =================
#define SA_F (128*36)
#define SW_F (32*136)
#define STG_F (SA_F + SW_F)          // 8960 floats = 35840 B per stage
#define TF_SMEM (3 * STG_F * 4)      // 107520 B

template<bool BIAS>
__global__ __launch_bounds__(256, 1) void tf32_gemm(
    const float* __restrict__ A, const float* __restrict__ W,
    const float* __restrict__ bias, float* __restrict__ C,
    int Mvalid, int N, int K)
{
    extern __shared__ float sm[];
    const int tid = threadIdx.x, lane = tid & 31, wid = tid >> 5;
    const int gid = lane >> 2, tig = lane & 3;
    const int wm = wid >> 2, wn = wid & 3;
    const int m0 = blockIdx.y * 128, n0 = blockIdx.x * 128;
    const uint32_t sb = smem_u32(sm);

    float acc[4][4][4];
    #pragma unroll
    for (int a = 0; a < 4; a++)
        #pragma unroll
        for (int b = 0; b < 4; b++)
            #pragma unroll
            for (int c = 0; c < 4; c++) acc[a][b][c] = 0.0f;

    const int S = K >> 5;

    #pragma unroll 1
    for (int s = 0; s < 2; s++) {
        const int k0 = s * 32;
        const uint32_t st = sb + (uint32_t)(s * STG_F * 4);
        #pragma unroll
        for (int i = 0; i < 4; i++) {
            int idx = i * 256 + tid;
            int ar = idx >> 3, ac = (idx & 7) * 4;
            cp16z(st + (uint32_t)(ar*36 + ac)*4, A + (size_t)(m0+ar)*K + k0 + ac,
                  (m0 + ar) < Mvalid);
        }
        #pragma unroll
        for (int i = 0; i < 4; i++) {
            int idx = i * 256 + tid;
            int wr = idx >> 5, wc = (idx & 31) * 4;
            cp16(st + (uint32_t)(SA_F + wr*136 + wc)*4, W + (size_t)(k0+wr)*N + n0 + wc);
        }
        asm volatile("cp.async.commit_group;" ::: "memory");
    }

    #pragma unroll 1
    for (int s = 0; s < S; s++) {
        asm volatile("cp.async.wait_group 1;" ::: "memory");
        __syncthreads();

        const int ns = s + 2;
        if (ns < S) {
            const int k0 = ns * 32;
            const uint32_t st = sb + (uint32_t)((ns % 3) * STG_F * 4);
            #pragma unroll
            for (int i = 0; i < 4; i++) {
                int idx = i * 256 + tid;
                int ar = idx >> 3, ac = (idx & 7) * 4;
                cp16z(st + (uint32_t)(ar*36 + ac)*4, A + (size_t)(m0+ar)*K + k0 + ac,
                      (m0 + ar) < Mvalid);
            }
            #pragma unroll
            for (int i = 0; i < 4; i++) {
                int idx = i * 256 + tid;
                int wr = idx >> 5, wc = (idx & 31) * 4;
                cp16(st + (uint32_t)(SA_F + wr*136 + wc)*4, W + (size_t)(k0+wr)*N + n0 + wc);
            }
        }
        asm volatile("cp.async.commit_group;" ::: "memory");

        const float* sA = sm + (s % 3) * STG_F;
        const float* sW = sA + SA_F;

        #pragma unroll
        for (int ks = 0; ks < 4; ks++) {
            uint32_t ahi[4][4], alo[4][4];
            #pragma unroll
            for (int mi = 0; mi < 4; mi++) {
                const int r0 = wm*64 + mi*16 + gid;
                const int c  = ks*8 + tig;
                split_tf(sA[r0*36 + c],       ahi[mi][0], alo[mi][0]);
                split_tf(sA[(r0+8)*36 + c],   ahi[mi][1], alo[mi][1]);
                split_tf(sA[r0*36 + c + 4],   ahi[mi][2], alo[mi][2]);
                split_tf(sA[(r0+8)*36 + c+4], ahi[mi][3], alo[mi][3]);
            }
            #pragma unroll
            for (int nj = 0; nj < 4; nj++) {
                const int kr = ks*8 + tig;
                const int bn = wn*32 + nj*8 + gid;
                uint32_t bh0, bl0, bh1, bl1;
                split_tf(sW[kr*136 + bn],     bh0, bl0);
                split_tf(sW[(kr+4)*136 + bn], bh1, bl1);
                #pragma unroll
                for (int mi = 0; mi < 4; mi++) {
                    mma_tf32(acc[mi][nj], ahi[mi], bh0, bh1);
                    mma_tf32(acc[mi][nj], ahi[mi], bl0, bl1);
                    mma_tf32(acc[mi][nj], alo[mi], bh0, bh1);
                }
            }
        }
    }

    #pragma unroll
    for (int mi = 0; mi < 4; mi++) {
        const int r0 = m0 + wm*64 + mi*16 + gid;
        #pragma unroll
        for (int nj = 0; nj < 4; nj++) {
            const int col = n0 + wn*32 + nj*8 + tig*2;
            float2 v0 = make_float2(acc[mi][nj][0], acc[mi][nj][1]);
            float2 v1 = make_float2(acc[mi][nj][2], acc[mi][nj][3]);
            if (BIAS) {
                float bx = bias[col], by = bias[col+1];
                v0.x += bx; v0.y += by; v1.x += bx; v1.y += by;
            }
            if (r0 < Mvalid)     *(float2*)&C[(size_t)r0 * N + col] = v0;
            if (r0 + 8 < Mvalid) *(float2*)&C[(size_t)(r0+8) * N + col] = v1;
        }
    }
}

// ---------------- Router: adaptive avg pool of q (32x32 -> 5x5) ----------------
__global__ void router_kernel(const float* __restrict__ qkv, float* __restrict__ router) {
    const int m = blockIdx.x, b = blockIdx.y;
    const int i = m / 5, j = m % 5;
    const int s[5] = {0, 6, 12, 19, 25};
    const int e[5] = {7, 13, 20, 26, 32};
    const float inv = 1.0f / (float)((e[i]-s[i]) * (e[j]-s[j]));
    for (int c = threadIdx.x; c < CC; c += blockDim.x) {
        float acc = 0.0f;
        for (int gh = s[i]; gh < e[i]; gh++)
            for (int gw = s[j]; gw < e[j]; gw++)
                acc += qkv[(size_t)(b*NN + gh*32 + gw) * QKVLD + c];
        router[(size_t)(b*MM + m) * CC + c] = acc * inv;
    }
}

// ---------------- r_logits = r@k^T, gate = r@q^T ----------------
__global__ void rg_kernel(const float* __restrict__ qkv, const float* __restrict__ router,
                          float* __restrict__ rlog, float* __restrict__ gate) {
    const int bh = blockIdx.y;
    const int b = bh >> 4, h = bh & 15;
    const int t0 = blockIdx.x * 256;
    const int tid = threadIdx.x;
    __shared__ float rsm[25][64];
    __shared__ float ks[256][17];
    __shared__ float qs[256][17];

    for (int idx = tid; idx < 1600; idx += 256)
        rsm[idx >> 6][idx & 63] = router[(size_t)(b*MM + (idx >> 6)) * CC + h*64 + (idx & 63)];

    float acc_k[25], acc_q[25];
    #pragma unroll
    for (int m = 0; m < 25; m++) { acc_k[m] = 0.0f; acc_q[m] = 0.0f; }

    const int n = t0 + tid;
    for (int dc = 0; dc < 64; dc += 16) {
        __syncthreads();
        for (int idx = tid; idx < 256*16; idx += 256) {
            int tok = idx >> 4, dd = idx & 15;
            int gn = t0 + tok;
            float kv = 0.0f, qv = 0.0f;
            if (gn < NN) {
                const float* base = qkv + (size_t)(b*NN + gn) * QKVLD + h*64 + dc + dd;
                qv = base[0];
                kv = base[1024];
            }
            ks[tok][dd] = kv; qs[tok][dd] = qv;
        }
        __syncthreads();
        #pragma unroll
        for (int d = 0; d < 16; d++) {
            float kd = ks[tid][d], qd = qs[tid][d];
            #pragma unroll
            for (int m = 0; m < 25; m++) {
                float r = rsm[m][dc + d];
                acc_k[m] += r * kd;
                acc_q[m] += r * qd;
            }
        }
    }
    if (n < NN) {
        #pragma unroll
        for (int m = 0; m < 25; m++) {
            rlog[((size_t)bh*MM + m) * NN + n] = acc_k[m];
            gate[((size_t)bh*MM + m) * NN + n] = acc_q[m];
        }
    }
}

// ---------------- Agent branch: softmax(r_logits*scale) @ V ----------------
__global__ void agent_kernel(const float* __restrict__ rlog, const float* __restrict__ qkv,
                             float* __restrict__ av) {
    const int bhm = blockIdx.x;
    const int bh = bhm / 25;
    const int b = bh >> 4, h = bh & 15;
    const float* row = rlog + (size_t)bhm * NN;
    __shared__ float p[NN];
    __shared__ float red[256];
    __shared__ float part[4][64];
    const int tid = threadIdx.x;      // 256

    float mx = -INFINITY;
    for (int n = tid; n < NN; n += 256) mx = fmaxf(mx, row[n]);
    red[tid] = mx; __syncthreads();
    for (int s = 128; s > 0; s >>= 1) {
        if (tid < s) red[tid] = fmaxf(red[tid], red[tid + s]);
        __syncthreads();
    }
    mx = red[0];
    __syncthreads();

    float sum = 0.0f;
    for (int n = tid; n < NN; n += 256) {
        float e = __expf((row[n] - mx) * SCALE);
        p[n] = e; sum += e;
    }
    red[tid] = sum; __syncthreads();
    for (int s = 128; s > 0; s >>= 1) {
        if (tid < s) red[tid] += red[tid + s];
        __syncthreads();
    }
    const float inv = 1.0f / red[0];

    const int g = tid >> 6, d = tid & 63;
    const float* vb = qkv + (size_t)b*NN*QKVLD + 2048 + h*64 + d;
    float acc = 0.0f;
    #pragma unroll 8
    for (int n = g; n < NN; n += 4) acc += p[n] * vb[(size_t)n * QKVLD];
    part[g][d] = acc;
    __syncthreads();
    if (tid < 64)
        av[(size_t)bhm * 64 + tid] =
            (part[0][tid] + part[1][tid] + part[2][tid] + part[3][tid]) * inv;
}

// ---------------- Top-25 key indices per (bh,m) ----------------
__global__ void topk_kernel(const float* __restrict__ rlog, int* __restrict__ topk) {
    const int bhm = blockIdx.x;
    __shared__ float vals[NN];
    __shared__ float bmax[256];
    __shared__ int bidx[256];
    const int tid = threadIdx.x;
    for (int n = tid; n < NN; n += 256) vals[n] = rlog[(size_t)bhm * NN + n];
    __syncthreads();
    for (int it = 0; it < 25; it++) {
        float best = -INFINITY; int bi = NN;
        for (int n = tid; n < NN; n += 256) {
            float v = vals[n];
            if (v > best || (v == best && n < bi)) { best = v; bi = n; }
        }
        bmax[tid] = best; bidx[tid] = bi; __syncthreads();
        for (int s = 128; s > 0; s >>= 1) {
            if (tid < s) {
                if (bmax[tid+s] > bmax[tid] ||
                    (bmax[tid+s] == bmax[tid] && bidx[tid+s] < bidx[tid])) {
                    bmax[tid] = bmax[tid+s]; bidx[tid] = bidx[tid+s];
                }
            }
            __syncthreads();
        }
        if (tid == 0) {
            topk[bhm * 25 + it] = bidx[0];
            vals[bidx[0]] = -INFINITY;
        }
        __syncthreads();
    }
}

// ---------------- Per-query expert argmax ----------------
__global__ void expert_kernel(const float* __restrict__ gate, int* __restrict__ expert) {
    const int idx = blockIdx.x * 256 + threadIdx.x;
    if (idx >= BB*HH*NN) return;
    const int bh = idx / NN, n = idx % NN;
    const float* g = gate + (size_t)bh * MM * NN + n;
    float best = g[0]; int bi = 0;
    #pragma unroll
    for (int m = 1; m < 25; m++) {
        float v = g[(size_t)m * NN];
        if (v > best) { best = v; bi = m; }
    }
    expert[idx] = bi;
}

// ---------------- Mixed attention ----------------
__global__ void mixed_kernel(const float* __restrict__ qkv, const float* __restrict__ gate,
                             const float* __restrict__ av, const int* __restrict__ topk,
                             const int* __restrict__ expert, float* __restrict__ attn) {
    const int bh = blockIdx.y;
    const int b = bh >> 4, h = bh & 15;
    const int tid = threadIdx.x, lane = tid & 31, w = tid >> 5;
    __shared__ float avs[25][64];
    __shared__ float ws[8][50];
    for (int idx = tid; idx < 1600; idx += 256)
        avs[idx >> 6][idx & 63] = av[(size_t)bh * 1600 + idx];
    __syncthreads();

    const int n = blockIdx.x * 8 + w;
    if (n >= NN) return;

    const int e = expert[bh * NN + n];
    const int sel = (lane < 25) ? topk[((size_t)bh*MM + e) * 25 + lane] : 0;

    const float* qrow = qkv + (size_t)(b*NN + n) * QKVLD + h*64;
    const float qa = qrow[lane], qb = qrow[lane + 32];
    const float* kb = qkv + (size_t)b*NN*QKVLD + 1024 + h*64;
    const float* vb = qkv + (size_t)b*NN*QKVLD + 2048 + h*64;

    float L0 = -INFINITY, L1 = -INFINITY;
    if (lane < 25) L0 = gate[((size_t)bh*MM + lane) * NN + n] * SCALE;

    #pragma unroll
    for (int k = 0; k < 25; k++) {
        int s = __shfl_sync(0xffffffffu, sel, k);
        const float* kr = kb + (size_t)s * QKVLD;
        float part = qa * kr[lane] + qb * kr[lane + 32];
        #pragma unroll
        for (int o = 16; o > 0; o >>= 1) part += __shfl_xor_sync(0xffffffffu, part, o);
        part *= SCALE;
        const int j = 25 + k;
        if (j < 32) { if (lane == j) L0 = part; }
        else        { if (lane == j - 32) L1 = part; }
    }

    float mx = fmaxf(L0, L1);
    #pragma unroll
    for (int o = 16; o > 0; o >>= 1) mx = fmaxf(mx, __shfl_xor_sync(0xffffffffu, mx, o));
    float p0 = __expf(L0 - mx), p1 = __expf(L1 - mx);
    float ssum = p0 + p1;
    #pragma unroll
    for (int o = 16; o > 0; o >>= 1) ssum += __shfl_xor_sync(0xffffffffu, ssum, o);
    const float invs = 1.0f / ssum;

    ws[w][lane] = p0 * invs;
    if (lane < 18) ws[w][32 + lane] = p1 * invs;
    __syncwarp();

    float o0 = 0.0f, o1 = 0.0f;
    #pragma unroll
    for (int m = 0; m < 25; m++) {
        float wt = ws[w][m];
        o0 += wt * avs[m][lane];
        o1 += wt * avs[m][lane + 32];
    }
    #pragma unroll
    for (int k = 0; k < 25; k++) {
        float wt = ws[w][25 + k];
        int s = __shfl_sync(0xffffffffu, sel, k);
        const float* vr = vb + (size_t)s * QKVLD;
        o0 += wt * vr[lane];
        o1 += wt * vr[lane + 32];
    }
    attn[(size_t)(b*NN + n) * CC + h*64 + lane] = o0;
    attn[(size_t)(b*NN + n) * CC + h*64 + lane + 32] = o1;
}

// ---------------- launch ----------------
extern "C" void kernel_launch(void* const* d_in, const int* in_sizes, int n_in,
                              void* d_out, int out_size) {
    const float* x     = (const float*)d_in[0];   // [8,1025,1024]
    const float* Wqkv  = (const float*)d_in[1];   // [1024,3072]
    const float* Wproj = (const float*)d_in[2];   // [1024,1024]
    const float* bproj = (const float*)d_in[3];   // [1024]
    float* out = (float*)d_out;                   // [8,1025,1024]

    float *qkv_p, *router_p, *rlog_p, *gate_p, *av_p, *attn_p;
    int *topk_p, *expert_p;
    cudaGetSymbolAddress((void**)&qkv_p,    g_qkv);
    cudaGetSymbolAddress((void**)&router_p, g_router);
    cudaGetSymbolAddress((void**)&rlog_p,   g_rlog);
    cudaGetSymbolAddress((void**)&gate_p,   g_gate);
    cudaGetSymbolAddress((void**)&av_p,     g_av);
    cudaGetSymbolAddress((void**)&topk_p,   g_topk);
    cudaGetSymbolAddress((void**)&expert_p, g_expert);
    cudaGetSymbolAddress((void**)&attn_p,   g_attn);

    cudaFuncSetAttribute(fgemm,
                         cudaFuncAttributeMaxDynamicSharedMemorySize, GEMM_SMEM);
    cudaFuncSetAttribute(tf32_gemm<true>,
                         cudaFuncAttributeMaxDynamicSharedMemorySize, TF_SMEM);

    // 1) qkv = x @ Wqkv (fp32 — selections depend on this; must be exact-grade)
    fgemm<<<dim3(QKVLD/128, (TOT+127)/128), 256, GEMM_SMEM>>>(
        x, Wqkv, qkv_p, TOT, QKVLD, CC);

    // 2) router tokens
    router_kernel<<<dim3(MM, BB), 256>>>(qkv_p, router_p);

    // 3) r_logits and gate
    rg_kernel<<<dim3((NN+255)/256, BB*HH), 256>>>(qkv_p, router_p, rlog_p, gate_p);

    // 4) agent values
    agent_kernel<<<BB*HH*MM, 256>>>(rlog_p, qkv_p, av_p);

    // 5) top-25 keys per expert
    topk_kernel<<<BB*HH*MM, 256>>>(rlog_p, topk_p);

    // 6) per-query expert
    expert_kernel<<<(BB*HH*NN + 255)/256, 256>>>(gate_p, expert_p);

    // 7) mixed attention
    mixed_kernel<<<dim3((NN+7)/8, BB*HH), 256>>>(qkv_p, gate_p, av_p, topk_p, expert_p, attn_p);

    // 8) out = attn @ Wproj + bproj (3xTF32 — no discrete consumers, flip-immune)
    tf32_gemm<true><<<dim3(CC/128, (TOT+127)/128), 256, TF_SMEM>>>(
        attn_p, Wproj, bproj, out, TOT, CC, CC);
}

// round 7
// speedup vs baseline: 1.2473x; 1.1707x over previous
#include <cuda_runtime.h>
#include <cuda_bf16.h>
#include <math.h>
#include <cstdint>

#define BB 8
#define NN 1025
#define CC 1024
#define HH 16
#define MM 25
#define TOT (BB*NN)           // 8200
#define QKVLD 3072
#define SCALE 0.125f

// ---------------- scratch (static device globals) ----------------
__device__ float g_qkv[TOT * QKVLD];
__device__ float g_router[BB * MM * CC];
__device__ float g_rlog[BB * HH * MM * NN];
__device__ float g_gate[BB * HH * MM * NN];
__device__ float g_av[BB * HH * MM * 64];
__device__ int   g_topk[BB * HH * MM * 25];
__device__ float g_attn[TOT * CC];

// ================= PTX helpers =================
__device__ __forceinline__ uint32_t smem_u32(const void* p) {
    return (uint32_t)__cvta_generic_to_shared(p);
}
__device__ __forceinline__ void cp16(uint32_t saddr, const void* g) {
    asm volatile("cp.async.cg.shared.global [%0], [%1], 16;" :: "r"(saddr), "l"(g));
}
__device__ __forceinline__ void cp16z(uint32_t saddr, const void* g, bool ok) {
    int sz = ok ? 16 : 0;
    asm volatile("cp.async.cg.shared.global [%0], [%1], 16, %2;"
                 :: "r"(saddr), "l"(g), "r"(sz));
}
__device__ __forceinline__ uint32_t f2tf(float v) {
    uint32_t r; asm("cvt.rna.tf32.f32 %0, %1;" : "=r"(r) : "f"(v)); return r;
}
__device__ __forceinline__ void split_tf(float v, uint32_t& hi, uint32_t& lo) {
    hi = f2tf(v);
    lo = f2tf(v - __uint_as_float(hi));
}
__device__ __forceinline__ void mma_tf32(float* c, const uint32_t* a, uint32_t b0, uint32_t b1) {
    asm volatile("mma.sync.aligned.m16n8k8.row.col.f32.tf32.tf32.f32 "
        "{%0,%1,%2,%3}, {%4,%5,%6,%7}, {%8,%9}, {%0,%1,%2,%3};"
        : "+f"(c[0]), "+f"(c[1]), "+f"(c[2]), "+f"(c[3])
        : "r"(a[0]), "r"(a[1]), "r"(a[2]), "r"(a[3]), "r"(b0), "r"(b1));
}

// ================= FP32 GEMM (GEMM1): 128x128x8, smem double-buffer + reg prefetch =================
__global__ __launch_bounds__(256) void sgemm_db(
    const float* __restrict__ A, const float* __restrict__ W,
    float* __restrict__ C, int M, int N, int K)
{
    __shared__ float As[2][8][128];
    __shared__ float Bs[2][8][128];
    const int tid = threadIdx.x;
    const int tx = tid & 15, ty = tid >> 4;
    const int brow = blockIdx.y * 128, bcol = blockIdx.x * 128;

    const int arow = tid >> 1, acol = (tid & 1) * 4;
    const int bkrow = tid >> 5, bncol = (tid & 31) * 4;

    const bool aok = (brow + arow) < M;
    const float* Ap = A + (size_t)(brow + arow) * K + acol;
    const float* Bp = W + (size_t)bkrow * N + bcol + bncol;

    float acc[8][8];
    #pragma unroll
    for (int i = 0; i < 8; i++)
        #pragma unroll
        for (int j = 0; j < 8; j++) acc[i][j] = 0.0f;

    float4 av = aok ? *(const float4*)Ap : make_float4(0.f,0.f,0.f,0.f);
    float4 bv = *(const float4*)Bp;
    As[0][acol+0][arow] = av.x; As[0][acol+1][arow] = av.y;
    As[0][acol+2][arow] = av.z; As[0][acol+3][arow] = av.w;
    *(float4*)&Bs[0][bkrow][bncol] = bv;
    __syncthreads();

    const int S = K >> 3;
    #pragma unroll 1
    for (int s = 0; s < S; s++) {
        const int cur = s & 1;
        if (s + 1 < S) {
            av = aok ? *(const float4*)(Ap + (s + 1) * 8) : make_float4(0.f,0.f,0.f,0.f);
            bv = *(const float4*)(Bp + (size_t)(s + 1) * 8 * N);
        }
        #pragma unroll
        for (int k = 0; k < 8; k++) {
            float4 a0 = ((const float4*)As[cur][k])[ty];
            float4 a1 = ((const float4*)As[cur][k])[16 + ty];
            float4 b0 = ((const float4*)Bs[cur][k])[tx];
            float4 b1 = ((const float4*)Bs[cur][k])[16 + tx];
            float a[8] = {a0.x,a0.y,a0.z,a0.w,a1.x,a1.y,a1.z,a1.w};
            float b[8] = {b0.x,b0.y,b0.z,b0.w,b1.x,b1.y,b1.z,b1.w};
            #pragma unroll
            for (int i = 0; i < 8; i++)
                #pragma unroll
                for (int j = 0; j < 8; j++)
                    acc[i][j] += a[i] * b[j];
        }
        if (s + 1 < S) {
            const int nxt = cur ^ 1;
            As[nxt][acol+0][arow] = av.x; As[nxt][acol+1][arow] = av.y;
            As[nxt][acol+2][arow] = av.z; As[nxt][acol+3][arow] = av.w;
            *(float4*)&Bs[nxt][bkrow][bncol] = bv;
        }
        __syncthreads();
    }

    #pragma unroll
    for (int i = 0; i < 8; i++) {
        int r = brow + (i < 4 ? ty*4 + i : 64 + ty*4 + (i-4));
        if (r >= M) continue;
        int c0 = bcol + tx*4;
        int c1 = bcol + 64 + tx*4;
        float4 o0, o1;
        o0.x = acc[i][0]; o0.y = acc[i][1]; o0.z = acc[i][2]; o0.w = acc[i][3];
        o1.x = acc[i][4]; o1.y = acc[i][5]; o1.z = acc[i][6]; o1.w = acc[i][7];
        *(float4*)&C[(size_t)r * N + c0] = o0;
        *(float4*)&C[(size_t)r * N + c1] = o1;
    }
}

// ================= 3xTF32 GEMM (GEMM2 — flip-immune, feeds final output) =================
#define SA_F (128*36)
#define SW_F (32*136)
#define STG_F (SA_F + SW_F)          // 8960 floats = 35840 B per stage
#define TF_SMEM (3 * STG_F * 4)      // 107520 B

template<bool BIAS>
__global__ __launch_bounds__(256, 1) void tf32_gemm(
    const float* __restrict__ A, const float* __restrict__ W,
    const float* __restrict__ bias, float* __restrict__ C,
    int Mvalid, int N, int K)
{
    extern __shared__ float sm[];
    const int tid = threadIdx.x, lane = tid & 31, wid = tid >> 5;
    const int gid = lane >> 2, tig = lane & 3;
    const int wm = wid >> 2, wn = wid & 3;
    const int m0 = blockIdx.y * 128, n0 = blockIdx.x * 128;
    const uint32_t sb = smem_u32(sm);

    float acc[4][4][4];
    #pragma unroll
    for (int a = 0; a < 4; a++)
        #pragma unroll
        for (int b = 0; b < 4; b++)
            #pragma unroll
            for (int c = 0; c < 4; c++) acc[a][b][c] = 0.0f;

    const int S = K >> 5;

    #pragma unroll 1
    for (int s = 0; s < 2; s++) {
        const int k0 = s * 32;
        const uint32_t st = sb + (uint32_t)(s * STG_F * 4);
        #pragma unroll
        for (int i = 0; i < 4; i++) {
            int idx = i * 256 + tid;
            int ar = idx >> 3, ac = (idx & 7) * 4;
            cp16z(st + (uint32_t)(ar*36 + ac)*4, A + (size_t)(m0+ar)*K + k0 + ac,
                  (m0 + ar) < Mvalid);
        }
        #pragma unroll
        for (int i = 0; i < 4; i++) {
            int idx = i * 256 + tid;
            int wr = idx >> 5, wc = (idx & 31) * 4;
            cp16(st + (uint32_t)(SA_F + wr*136 + wc)*4, W + (size_t)(k0+wr)*N + n0 + wc);
        }
        asm volatile("cp.async.commit_group;" ::: "memory");
    }

    #pragma unroll 1
    for (int s = 0; s < S; s++) {
        asm volatile("cp.async.wait_group 1;" ::: "memory");
        __syncthreads();

        const int ns = s + 2;
        if (ns < S) {
            const int k0 = ns * 32;
            const uint32_t st = sb + (uint32_t)((ns % 3) * STG_F * 4);
            #pragma unroll
            for (int i = 0; i < 4; i++) {
                int idx = i * 256 + tid;
                int ar = idx >> 3, ac = (idx & 7) * 4;
                cp16z(st + (uint32_t)(ar*36 + ac)*4, A + (size_t)(m0+ar)*K + k0 + ac,
                      (m0 + ar) < Mvalid);
            }
            #pragma unroll
            for (int i = 0; i < 4; i++) {
                int idx = i * 256 + tid;
                int wr = idx >> 5, wc = (idx & 31) * 4;
                cp16(st + (uint32_t)(SA_F + wr*136 + wc)*4, W + (size_t)(k0+wr)*N + n0 + wc);
            }
        }
        asm volatile("cp.async.commit_group;" ::: "memory");

        const float* sA = sm + (s % 3) * STG_F;
        const float* sW = sA + SA_F;

        #pragma unroll
        for (int ks = 0; ks < 4; ks++) {
            uint32_t ahi[4][4], alo[4][4];
            #pragma unroll
            for (int mi = 0; mi < 4; mi++) {
                const int r0 = wm*64 + mi*16 + gid;
                const int c  = ks*8 + tig;
                split_tf(sA[r0*36 + c],       ahi[mi][0], alo[mi][0]);
                split_tf(sA[(r0+8)*36 + c],   ahi[mi][1], alo[mi][1]);
                split_tf(sA[r0*36 + c + 4],   ahi[mi][2], alo[mi][2]);
                split_tf(sA[(r0+8)*36 + c+4], ahi[mi][3], alo[mi][3]);
            }
            #pragma unroll
            for (int nj = 0; nj < 4; nj++) {
                const int kr = ks*8 + tig;
                const int bn = wn*32 + nj*8 + gid;
                uint32_t bh0, bl0, bh1, bl1;
                split_tf(sW[kr*136 + bn],     bh0, bl0);
                split_tf(sW[(kr+4)*136 + bn], bh1, bl1);
                #pragma unroll
                for (int mi = 0; mi < 4; mi++) {
                    mma_tf32(acc[mi][nj], ahi[mi], bh0, bh1);
                    mma_tf32(acc[mi][nj], ahi[mi], bl0, bl1);
                    mma_tf32(acc[mi][nj], alo[mi], bh0, bh1);
                }
            }
        }
    }

    #pragma unroll
    for (int mi = 0; mi < 4; mi++) {
        const int r0 = m0 + wm*64 + mi*16 + gid;
        #pragma unroll
        for (int nj = 0; nj < 4; nj++) {
            const int col = n0 + wn*32 + nj*8 + tig*2;
            float2 v0 = make_float2(acc[mi][nj][0], acc[mi][nj][1]);
            float2 v1 = make_float2(acc[mi][nj][2], acc[mi][nj][3]);
            if (BIAS) {
                float bx = bias[col], by = bias[col+1];
                v0.x += bx; v0.y += by; v1.x += bx; v1.y += by;
            }
            if (r0 < Mvalid)     *(float2*)&C[(size_t)r0 * N + col] = v0;
            if (r0 + 8 < Mvalid) *(float2*)&C[(size_t)(r0+8) * N + col] = v1;
        }
    }
}

// ---------------- Router: adaptive avg pool of q (32x32 -> 5x5) ----------------
__global__ void router_kernel(const float* __restrict__ qkv, float* __restrict__ router) {
    const int m = blockIdx.x, b = blockIdx.y;
    const int i = m / 5, j = m % 5;
    const int s[5] = {0, 6, 12, 19, 25};
    const int e[5] = {7, 13, 20, 26, 32};
    const float inv = 1.0f / (float)((e[i]-s[i]) * (e[j]-s[j]));
    for (int c = threadIdx.x; c < CC; c += blockDim.x) {
        float acc = 0.0f;
        for (int gh = s[i]; gh < e[i]; gh++)
            for (int gw = s[j]; gw < e[j]; gw++)
                acc += qkv[(size_t)(b*NN + gh*32 + gw) * QKVLD + c];
        router[(size_t)(b*MM + m) * CC + c] = acc * inv;
    }
}

// ---------------- r_logits = r@k^T, gate = r@q^T ----------------
__global__ void rg_kernel(const float* __restrict__ qkv, const float* __restrict__ router,
                          float* __restrict__ rlog, float* __restrict__ gate) {
    const int bh = blockIdx.y;
    const int b = bh >> 4, h = bh & 15;
    const int t0 = blockIdx.x * 256;
    const int tid = threadIdx.x;
    __shared__ float rsm[25][64];
    __shared__ float ks[256][17];
    __shared__ float qs[256][17];

    for (int idx = tid; idx < 1600; idx += 256)
        rsm[idx >> 6][idx & 63] = router[(size_t)(b*MM + (idx >> 6)) * CC + h*64 + (idx & 63)];

    float acc_k[25], acc_q[25];
    #pragma unroll
    for (int m = 0; m < 25; m++) { acc_k[m] = 0.0f; acc_q[m] = 0.0f; }

    const int n = t0 + tid;
    for (int dc = 0; dc < 64; dc += 16) {
        __syncthreads();
        for (int idx = tid; idx < 256*16; idx += 256) {
            int tok = idx >> 4, dd = idx & 15;
            int gn = t0 + tok;
            float kv = 0.0f, qv = 0.0f;
            if (gn < NN) {
                const float* base = qkv + (size_t)(b*NN + gn) * QKVLD + h*64 + dc + dd;
                qv = base[0];
                kv = base[1024];
            }
            ks[tok][dd] = kv; qs[tok][dd] = qv;
        }
        __syncthreads();
        #pragma unroll
        for (int d = 0; d < 16; d++) {
            float kd = ks[tid][d], qd = qs[tid][d];
            #pragma unroll
            for (int m = 0; m < 25; m++) {
                float r = rsm[m][dc + d];
                acc_k[m] += r * kd;
                acc_q[m] += r * qd;
            }
        }
    }
    if (n < NN) {
        #pragma unroll
        for (int m = 0; m < 25; m++) {
            rlog[((size_t)bh*MM + m) * NN + n] = acc_k[m];
            gate[((size_t)bh*MM + m) * NN + n] = acc_q[m];
        }
    }
}

// ---------------- Fused agent (softmax @ V) + top-25 per (bh,m) ----------------
__global__ void agent_topk_kernel(const float* __restrict__ rlog, const float* __restrict__ qkv,
                                  float* __restrict__ av, int* __restrict__ topk) {
    const int bhm = blockIdx.x;
    const int bh = bhm / 25;
    const int b = bh >> 4, h = bh & 15;
    const float* row = rlog + (size_t)bhm * NN;
    __shared__ float vals[NN];    // raw logits (destructive top-k)
    __shared__ float p[NN];       // softmax numerators
    __shared__ float red[256];
    __shared__ int   redi[256];
    __shared__ float part[4][64];
    const int tid = threadIdx.x;  // 256

    float mx = -INFINITY;
    for (int n = tid; n < NN; n += 256) {
        float v = row[n];
        vals[n] = v;
        mx = fmaxf(mx, v);
    }
    red[tid] = mx; __syncthreads();
    for (int s = 128; s > 0; s >>= 1) {
        if (tid < s) red[tid] = fmaxf(red[tid], red[tid + s]);
        __syncthreads();
    }
    mx = red[0];
    __syncthreads();

    float sum = 0.0f;
    for (int n = tid; n < NN; n += 256) {
        float e = __expf((vals[n] - mx) * SCALE);
        p[n] = e; sum += e;
    }
    red[tid] = sum; __syncthreads();
    for (int s = 128; s > 0; s >>= 1) {
        if (tid < s) red[tid] += red[tid + s];
        __syncthreads();
    }
    const float inv = 1.0f / red[0];
    __syncthreads();

    // agent value: softmax @ V (4-way split over n)
    const int g = tid >> 6, d = tid & 63;
    const float* vb = qkv + (size_t)b*NN*QKVLD + 2048 + h*64 + d;
    float acc = 0.0f;
    #pragma unroll 8
    for (int n = g; n < NN; n += 4) acc += p[n] * vb[(size_t)n * QKVLD];
    part[g][d] = acc;
    __syncthreads();
    if (tid < 64)
        av[(size_t)bhm * 64 + tid] =
            (part[0][tid] + part[1][tid] + part[2][tid] + part[3][tid]) * inv;

    // top-25 (destructive on vals)
    for (int it = 0; it < 25; it++) {
        float best = -INFINITY; int bi = NN;
        for (int n = tid; n < NN; n += 256) {
            float v = vals[n];
            if (v > best || (v == best && n < bi)) { best = v; bi = n; }
        }
        red[tid] = best; redi[tid] = bi; __syncthreads();
        for (int s = 128; s > 0; s >>= 1) {
            if (tid < s) {
                if (red[tid+s] > red[tid] ||
                    (red[tid+s] == red[tid] && redi[tid+s] < redi[tid])) {
                    red[tid] = red[tid+s]; redi[tid] = redi[tid+s];
                }
            }
            __syncthreads();
        }
        if (tid == 0) {
            topk[bhm * 25 + it] = redi[0];
            vals[redi[0]] = -INFINITY;
        }
        __syncthreads();
    }
}

// ---------------- Mixed attention (expert argmax fused in) ----------------
__global__ void mixed_kernel(const float* __restrict__ qkv, const float* __restrict__ gate,
                             const float* __restrict__ av, const int* __restrict__ topk,
                             float* __restrict__ attn) {
    const int bh = blockIdx.y;
    const int b = bh >> 4, h = bh & 15;
    const int tid = threadIdx.x, lane = tid & 31, w = tid >> 5;
    __shared__ float avs[25][64];
    __shared__ float ws[8][50];
    for (int idx = tid; idx < 1600; idx += 256)
        avs[idx >> 6][idx & 63] = av[(size_t)bh * 1600 + idx];
    __syncthreads();

    const int n = blockIdx.x * 8 + w;
    if (n >= NN) return;

    // gate value for this query at router m=lane
    float gv = (lane < 25) ? gate[((size_t)bh*MM + lane) * NN + n] : -INFINITY;

    // inline expert argmax (first-max tiebreak = lowest index)
    float bval = gv; int bidx = (lane < 25) ? lane : 1000;
    #pragma unroll
    for (int o = 16; o > 0; o >>= 1) {
        float ov = __shfl_xor_sync(0xffffffffu, bval, o);
        int   oi = __shfl_xor_sync(0xffffffffu, bidx, o);
        if (ov > bval || (ov == bval && oi < bidx)) { bval = ov; bidx = oi; }
    }
    const int e = bidx;

    const int sel = (lane < 25) ? topk[((size_t)bh*MM + e) * 25 + lane] : 0;

    const float* qrow = qkv + (size_t)(b*NN + n) * QKVLD + h*64;
    const float qa = qrow[lane], qb = qrow[lane + 32];
    const float* kb = qkv + (size_t)b*NN*QKVLD + 1024 + h*64;
    const float* vb = qkv + (size_t)b*NN*QKVLD + 2048 + h*64;

    float L0 = (lane < 25) ? gv * SCALE : -INFINITY;
    float L1 = -INFINITY;

    #pragma unroll
    for (int k = 0; k < 25; k++) {
        int s = __shfl_sync(0xffffffffu, sel, k);
        const float* kr = kb + (size_t)s * QKVLD;
        float part = qa * kr[lane] + qb * kr[lane + 32];
        #pragma unroll
        for (int o = 16; o > 0; o >>= 1) part += __shfl_xor_sync(0xffffffffu, part, o);
        part *= SCALE;
        const int j = 25 + k;
        if (j < 32) { if (lane == j) L0 = part; }
        else        { if (lane == j - 32) L1 = part; }
    }

    float mx = fmaxf(L0, L1);
    #pragma unroll
    for (int o = 16; o > 0; o >>= 1) mx = fmaxf(mx, __shfl_xor_sync(0xffffffffu, mx, o));
    float p0 = __expf(L0 - mx), p1 = __expf(L1 - mx);
    float ssum = p0 + p1;
    #pragma unroll
    for (int o = 16; o > 0; o >>= 1) ssum += __shfl_xor_sync(0xffffffffu, ssum, o);
    const float invs = 1.0f / ssum;

    ws[w][lane] = p0 * invs;
    if (lane < 18) ws[w][32 + lane] = p1 * invs;
    __syncwarp();

    float o0 = 0.0f, o1 = 0.0f;
    #pragma unroll
    for (int m = 0; m < 25; m++) {
        float wt = ws[w][m];
        o0 += wt * avs[m][lane];
        o1 += wt * avs[m][lane + 32];
    }
    #pragma unroll
    for (int k = 0; k < 25; k++) {
        float wt = ws[w][25 + k];
        int s = __shfl_sync(0xffffffffu, sel, k);
        const float* vr = vb + (size_t)s * QKVLD;
        o0 += wt * vr[lane];
        o1 += wt * vr[lane + 32];
    }
    attn[(size_t)(b*NN + n) * CC + h*64 + lane] = o0;
    attn[(size_t)(b*NN + n) * CC + h*64 + lane + 32] = o1;
}

// ---------------- launch ----------------
extern "C" void kernel_launch(void* const* d_in, const int* in_sizes, int n_in,
                              void* d_out, int out_size) {
    const float* x     = (const float*)d_in[0];   // [8,1025,1024]
    const float* Wqkv  = (const float*)d_in[1];   // [1024,3072]
    const float* Wproj = (const float*)d_in[2];   // [1024,1024]
    const float* bproj = (const float*)d_in[3];   // [1024]
    float* out = (float*)d_out;                   // [8,1025,1024]

    float *qkv_p, *router_p, *rlog_p, *gate_p, *av_p, *attn_p;
    int *topk_p;
    cudaGetSymbolAddress((void**)&qkv_p,    g_qkv);
    cudaGetSymbolAddress((void**)&router_p, g_router);
    cudaGetSymbolAddress((void**)&rlog_p,   g_rlog);
    cudaGetSymbolAddress((void**)&gate_p,   g_gate);
    cudaGetSymbolAddress((void**)&av_p,     g_av);
    cudaGetSymbolAddress((void**)&topk_p,   g_topk);
    cudaGetSymbolAddress((void**)&attn_p,   g_attn);

    cudaFuncSetAttribute(tf32_gemm<true>,
                         cudaFuncAttributeMaxDynamicSharedMemorySize, TF_SMEM);

    // 1) qkv = x @ Wqkv (fp32, double-buffered — selections need fp32-grade)
    sgemm_db<<<dim3(QKVLD/128, (TOT+127)/128), 256>>>(
        x, Wqkv, qkv_p, TOT, QKVLD, CC);

    // 2) router tokens
    router_kernel<<<dim3(MM, BB), 256>>>(qkv_p, router_p);

    // 3) r_logits and gate
    rg_kernel<<<dim3((NN+255)/256, BB*HH), 256>>>(qkv_p, router_p, rlog_p, gate_p);

    // 4) fused agent values + top-25
    agent_topk_kernel<<<BB*HH*MM, 256>>>(rlog_p, qkv_p, av_p, topk_p);

    // 5) mixed attention (expert argmax inlined)
    mixed_kernel<<<dim3((NN+7)/8, BB*HH), 256>>>(qkv_p, gate_p, av_p, topk_p, attn_p);

    // 6) out = attn @ Wproj + bproj (3xTF32 — flip-immune)
    tf32_gemm<true><<<dim3(CC/128, (TOT+127)/128), 256, TF_SMEM>>>(
        attn_p, Wproj, bproj, out, TOT, CC, CC);
}

// round 9
// speedup vs baseline: 1.2574x; 1.0081x over previous
#include <cuda_runtime.h>
#include <cuda_bf16.h>
#include <math.h>
#include <cstdint>

#define BB 8
#define NN 1025
#define CC 1024
#define HH 16
#define MM 25
#define TOT (BB*NN)           // 8200
#define QKVLD 3072
#define SCALE 0.125f

// ---------------- scratch (static device globals) ----------------
__device__ float g_qkv[TOT * QKVLD];
__device__ float g_router[BB * MM * CC];
__device__ float g_rlog[BB * HH * MM * NN];
__device__ float g_gate[BB * HH * MM * NN];
__device__ float g_av[BB * HH * MM * 64];
__device__ int   g_topk[BB * HH * MM * 25];
__device__ float g_attn[TOT * CC];

// ================= PTX helpers =================
__device__ __forceinline__ uint32_t smem_u32(const void* p) {
    return (uint32_t)__cvta_generic_to_shared(p);
}
__device__ __forceinline__ void cp16(uint32_t saddr, const void* g) {
    asm volatile("cp.async.cg.shared.global [%0], [%1], 16;" :: "r"(saddr), "l"(g));
}
__device__ __forceinline__ void cp16z(uint32_t saddr, const void* g, bool ok) {
    int sz = ok ? 16 : 0;
    asm volatile("cp.async.cg.shared.global [%0], [%1], 16, %2;"
                 :: "r"(saddr), "l"(g), "r"(sz));
}
__device__ __forceinline__ uint32_t f2tf(float v) {
    uint32_t r; asm("cvt.rna.tf32.f32 %0, %1;" : "=r"(r) : "f"(v)); return r;
}
__device__ __forceinline__ void split_tf(float v, uint32_t& hi, uint32_t& lo) {
    hi = f2tf(v);
    lo = f2tf(v - __uint_as_float(hi));
}
__device__ __forceinline__ void mma_tf32(float* c, const uint32_t* a, uint32_t b0, uint32_t b1) {
    asm volatile("mma.sync.aligned.m16n8k8.row.col.f32.tf32.tf32.f32 "
        "{%0,%1,%2,%3}, {%4,%5,%6,%7}, {%8,%9}, {%0,%1,%2,%3};"
        : "+f"(c[0]), "+f"(c[1]), "+f"(c[2]), "+f"(c[3])
        : "r"(a[0]), "r"(a[1]), "r"(a[2]), "r"(a[3]), "r"(b0), "r"(b1));
}

// ================= FP32 GEMM (q,k — selection-critical): 128x128x8 double-buffered =================
__global__ __launch_bounds__(256) void sgemm_db(
    const float* __restrict__ A, const float* __restrict__ W,
    float* __restrict__ C, int M, int N, int K)
{
    __shared__ float As[2][8][128];
    __shared__ float Bs[2][8][128];
    const int tid = threadIdx.x;
    const int tx = tid & 15, ty = tid >> 4;
    const int brow = blockIdx.y * 128, bcol = blockIdx.x * 128;

    const int arow = tid >> 1, acol = (tid & 1) * 4;
    const int bkrow = tid >> 5, bncol = (tid & 31) * 4;

    const bool aok = (brow + arow) < M;
    const float* Ap = A + (size_t)(brow + arow) * K + acol;
    const float* Bp = W + (size_t)bkrow * N + bcol + bncol;

    float acc[8][8];
    #pragma unroll
    for (int i = 0; i < 8; i++)
        #pragma unroll
        for (int j = 0; j < 8; j++) acc[i][j] = 0.0f;

    float4 av = aok ? *(const float4*)Ap : make_float4(0.f,0.f,0.f,0.f);
    float4 bv = *(const float4*)Bp;
    As[0][acol+0][arow] = av.x; As[0][acol+1][arow] = av.y;
    As[0][acol+2][arow] = av.z; As[0][acol+3][arow] = av.w;
    *(float4*)&Bs[0][bkrow][bncol] = bv;
    __syncthreads();

    const int S = K >> 3;
    #pragma unroll 1
    for (int s = 0; s < S; s++) {
        const int cur = s & 1;
        if (s + 1 < S) {
            av = aok ? *(const float4*)(Ap + (s + 1) * 8) : make_float4(0.f,0.f,0.f,0.f);
            bv = *(const float4*)(Bp + (size_t)(s + 1) * 8 * N);
        }
        #pragma unroll
        for (int k = 0; k < 8; k++) {
            float4 a0 = ((const float4*)As[cur][k])[ty];
            float4 a1 = ((const float4*)As[cur][k])[16 + ty];
            float4 b0 = ((const float4*)Bs[cur][k])[tx];
            float4 b1 = ((const float4*)Bs[cur][k])[16 + tx];
            float a[8] = {a0.x,a0.y,a0.z,a0.w,a1.x,a1.y,a1.z,a1.w};
            float b[8] = {b0.x,b0.y,b0.z,b0.w,b1.x,b1.y,b1.z,b1.w};
            #pragma unroll
            for (int i = 0; i < 8; i++)
                #pragma unroll
                for (int j = 0; j < 8; j++)
                    acc[i][j] += a[i] * b[j];
        }
        if (s + 1 < S) {
            const int nxt = cur ^ 1;
            As[nxt][acol+0][arow] = av.x; As[nxt][acol+1][arow] = av.y;
            As[nxt][acol+2][arow] = av.z; As[nxt][acol+3][arow] = av.w;
            *(float4*)&Bs[nxt][bkrow][bncol] = bv;
        }
        __syncthreads();
    }

    #pragma unroll
    for (int i = 0; i < 8; i++) {
        int r = brow + (i < 4 ? ty*4 + i : 64 + ty*4 + (i-4));
        if (r >= M) continue;
        int c0 = bcol + tx*4;
        int c1 = bcol + 64 + tx*4;
        float4 o0, o1;
        o0.x = acc[i][0]; o0.y = acc[i][1]; o0.z = acc[i][2]; o0.w = acc[i][3];
        o1.x = acc[i][4]; o1.y = acc[i][5]; o1.z = acc[i][6]; o1.w = acc[i][7];
        *(float4*)&C[(size_t)r * N + c0] = o0;
        *(float4*)&C[(size_t)r * N + c1] = o1;
    }
}

// ================= 3xTF32 GEMM (smooth paths only: v-projection, out-projection) =================
// N parameter = row stride of W and C; processed columns = gridDim.x*128 from the
// (already offset) W/C base pointers.
#define SA_F (128*36)
#define SW_F (32*136)
#define STG_F (SA_F + SW_F)          // 8960 floats = 35840 B per stage
#define TF_SMEM (3 * STG_F * 4)      // 107520 B

template<bool BIAS>
__global__ __launch_bounds__(256, 1) void tf32_gemm(
    const float* __restrict__ A, const float* __restrict__ W,
    const float* __restrict__ bias, float* __restrict__ C,
    int Mvalid, int N, int K)
{
    extern __shared__ float sm[];
    const int tid = threadIdx.x, lane = tid & 31, wid = tid >> 5;
    const int gid = lane >> 2, tig = lane & 3;
    const int wm = wid >> 2, wn = wid & 3;
    const int m0 = blockIdx.y * 128, n0 = blockIdx.x * 128;
    const uint32_t sb = smem_u32(sm);

    float acc[4][4][4];
    #pragma unroll
    for (int a = 0; a < 4; a++)
        #pragma unroll
        for (int b = 0; b < 4; b++)
            #pragma unroll
            for (int c = 0; c < 4; c++) acc[a][b][c] = 0.0f;

    const int S = K >> 5;

    #pragma unroll 1
    for (int s = 0; s < 2; s++) {
        const int k0 = s * 32;
        const uint32_t st = sb + (uint32_t)(s * STG_F * 4);
        #pragma unroll
        for (int i = 0; i < 4; i++) {
            int idx = i * 256 + tid;
            int ar = idx >> 3, ac = (idx & 7) * 4;
            cp16z(st + (uint32_t)(ar*36 + ac)*4, A + (size_t)(m0+ar)*K + k0 + ac,
                  (m0 + ar) < Mvalid);
        }
        #pragma unroll
        for (int i = 0; i < 4; i++) {
            int idx = i * 256 + tid;
            int wr = idx >> 5, wc = (idx & 31) * 4;
            cp16(st + (uint32_t)(SA_F + wr*136 + wc)*4, W + (size_t)(k0+wr)*N + n0 + wc);
        }
        asm volatile("cp.async.commit_group;" ::: "memory");
    }

    #pragma unroll 1
    for (int s = 0; s < S; s++) {
        asm volatile("cp.async.wait_group 1;" ::: "memory");
        __syncthreads();

        const int ns = s + 2;
        if (ns < S) {
            const int k0 = ns * 32;
            const uint32_t st = sb + (uint32_t)((ns % 3) * STG_F * 4);
            #pragma unroll
            for (int i = 0; i < 4; i++) {
                int idx = i * 256 + tid;
                int ar = idx >> 3, ac = (idx & 7) * 4;
                cp16z(st + (uint32_t)(ar*36 + ac)*4, A + (size_t)(m0+ar)*K + k0 + ac,
                      (m0 + ar) < Mvalid);
            }
            #pragma unroll
            for (int i = 0; i < 4; i++) {
                int idx = i * 256 + tid;
                int wr = idx >> 5, wc = (idx & 31) * 4;
                cp16(st + (uint32_t)(SA_F + wr*136 + wc)*4, W + (size_t)(k0+wr)*N + n0 + wc);
            }
        }
        asm volatile("cp.async.commit_group;" ::: "memory");

        const float* sA = sm + (s % 3) * STG_F;
        const float* sW = sA + SA_F;

        #pragma unroll
        for (int ks = 0; ks < 4; ks++) {
            uint32_t ahi[4][4], alo[4][4];
            #pragma unroll
            for (int mi = 0; mi < 4; mi++) {
                const int r0 = wm*64 + mi*16 + gid;
                const int c  = ks*8 + tig;
                split_tf(sA[r0*36 + c],       ahi[mi][0], alo[mi][0]);
                split_tf(sA[(r0+8)*36 + c],   ahi[mi][1], alo[mi][1]);
                split_tf(sA[r0*36 + c + 4],   ahi[mi][2], alo[mi][2]);
                split_tf(sA[(r0+8)*36 + c+4], ahi[mi][3], alo[mi][3]);
            }
            #pragma unroll
            for (int nj = 0; nj < 4; nj++) {
                const int kr = ks*8 + tig;
                const int bn = wn*32 + nj*8 + gid;
                uint32_t bh0, bl0, bh1, bl1;
                split_tf(sW[kr*136 + bn],     bh0, bl0);
                split_tf(sW[(kr+4)*136 + bn], bh1, bl1);
                #pragma unroll
                for (int mi = 0; mi < 4; mi++) {
                    mma_tf32(acc[mi][nj], ahi[mi], bh0, bh1);
                    mma_tf32(acc[mi][nj], ahi[mi], bl0, bl1);
                    mma_tf32(acc[mi][nj], alo[mi], bh0, bh1);
                }
            }
        }
    }

    #pragma unroll
    for (int mi = 0; mi < 4; mi++) {
        const int r0 = m0 + wm*64 + mi*16 + gid;
        #pragma unroll
        for (int nj = 0; nj < 4; nj++) {
            const int col = n0 + wn*32 + nj*8 + tig*2;
            float2 v0 = make_float2(acc[mi][nj][0], acc[mi][nj][1]);
            float2 v1 = make_float2(acc[mi][nj][2], acc[mi][nj][3]);
            if (BIAS) {
                float bx = bias[col], by = bias[col+1];
                v0.x += bx; v0.y += by; v1.x += bx; v1.y += by;
            }
            if (r0 < Mvalid)     *(float2*)&C[(size_t)r0 * N + col] = v0;
            if (r0 + 8 < Mvalid) *(float2*)&C[(size_t)(r0+8) * N + col] = v1;
        }
    }
}

// ---------------- Router: adaptive avg pool of q (32x32 -> 5x5) ----------------
__global__ void router_kernel(const float* __restrict__ qkv, float* __restrict__ router) {
    const int m = blockIdx.x, b = blockIdx.y;
    const int i = m / 5, j = m % 5;
    const int s[5] = {0, 6, 12, 19, 25};
    const int e[5] = {7, 13, 20, 26, 32};
    const float inv = 1.0f / (float)((e[i]-s[i]) * (e[j]-s[j]));
    for (int c = threadIdx.x; c < CC; c += blockDim.x) {
        float acc = 0.0f;
        for (int gh = s[i]; gh < e[i]; gh++)
            for (int gw = s[j]; gw < e[j]; gw++)
                acc += qkv[(size_t)(b*NN + gh*32 + gw) * QKVLD + c];
        router[(size_t)(b*MM + m) * CC + c] = acc * inv;
    }
}

// ---------------- r_logits = r@k^T, gate = r@q^T ----------------
__global__ void rg_kernel(const float* __restrict__ qkv, const float* __restrict__ router,
                          float* __restrict__ rlog, float* __restrict__ gate) {
    const int bh = blockIdx.y;
    const int b = bh >> 4, h = bh & 15;
    const int t0 = blockIdx.x * 256;
    const int tid = threadIdx.x;
    __shared__ float rsm[25][64];
    __shared__ float ks[256][17];
    __shared__ float qs[256][17];

    for (int idx = tid; idx < 1600; idx += 256)
        rsm[idx >> 6][idx & 63] = router[(size_t)(b*MM + (idx >> 6)) * CC + h*64 + (idx & 63)];

    float acc_k[25], acc_q[25];
    #pragma unroll
    for (int m = 0; m < 25; m++) { acc_k[m] = 0.0f; acc_q[m] = 0.0f; }

    const int n = t0 + tid;
    for (int dc = 0; dc < 64; dc += 16) {
        __syncthreads();
        for (int idx = tid; idx < 256*16; idx += 256) {
            int tok = idx >> 4, dd = idx & 15;
            int gn = t0 + tok;
            float kv = 0.0f, qv = 0.0f;
            if (gn < NN) {
                const float* base = qkv + (size_t)(b*NN + gn) * QKVLD + h*64 + dc + dd;
                qv = base[0];
                kv = base[1024];
            }
            ks[tok][dd] = kv; qs[tok][dd] = qv;
        }
        __syncthreads();
        #pragma unroll
        for (int d = 0; d < 16; d++) {
            float kd = ks[tid][d], qd = qs[tid][d];
            #pragma unroll
            for (int m = 0; m < 25; m++) {
                float r = rsm[m][dc + d];
                acc_k[m] += r * kd;
                acc_q[m] += r * qd;
            }
        }
    }
    if (n < NN) {
        #pragma unroll
        for (int m = 0; m < 25; m++) {
            rlog[((size_t)bh*MM + m) * NN + n] = acc_k[m];
            gate[((size_t)bh*MM + m) * NN + n] = acc_q[m];
        }
    }
}

// ---------------- Fused agent (softmax @ V) + register-resident top-25 ----------------
__global__ __launch_bounds__(256) void agent_topk_kernel(
    const float* __restrict__ rlog, const float* __restrict__ qkv,
    float* __restrict__ av, int* __restrict__ topk) {
    const int bhm = blockIdx.x;
    const int bh = bhm / 25;
    const int b = bh >> 4, h = bh & 15;
    const float* row = rlog + (size_t)bhm * NN;
    __shared__ float p[NN];
    __shared__ float red[256];
    __shared__ float part[4][64];
    __shared__ float wval[8];
    __shared__ int   widx[8];
    __shared__ int   swin;
    const int tid = threadIdx.x;  // 256
    const int lane = tid & 31, wrp = tid >> 5;

    float v[5];
    #pragma unroll
    for (int j = 0; j < 4; j++) v[j] = row[tid + j*256];
    v[4] = (tid == 0) ? row[1024] : -INFINITY;

    float mx = v[0];
    #pragma unroll
    for (int j = 1; j < 5; j++) mx = fmaxf(mx, v[j]);
    red[tid] = mx; __syncthreads();
    for (int s = 128; s > 0; s >>= 1) {
        if (tid < s) red[tid] = fmaxf(red[tid], red[tid + s]);
        __syncthreads();
    }
    mx = red[0];
    __syncthreads();

    float sum = 0.0f;
    #pragma unroll
    for (int j = 0; j < 4; j++) {
        float e = __expf((v[j] - mx) * SCALE);
        p[tid + j*256] = e; sum += e;
    }
    if (tid == 0) {
        float e = __expf((v[4] - mx) * SCALE);
        p[1024] = e; sum += e;
    }
    red[tid] = sum; __syncthreads();
    for (int s = 128; s > 0; s >>= 1) {
        if (tid < s) red[tid] += red[tid + s];
        __syncthreads();
    }
    const float inv = 1.0f / red[0];
    __syncthreads();

    const int g = tid >> 6, d = tid & 63;
    const float* vb = qkv + (size_t)b*NN*QKVLD + 2048 + h*64 + d;
    float acc = 0.0f;
    #pragma unroll 8
    for (int n = g; n < NN; n += 4) acc += p[n] * vb[(size_t)n * QKVLD];
    part[g][d] = acc;
    __syncthreads();
    if (tid < 64)
        av[(size_t)bhm * 64 + tid] =
            (part[0][tid] + part[1][tid] + part[2][tid] + part[3][tid]) * inv;

    for (int it = 0; it < 25; it++) {
        float bv = v[0]; int bi = tid;
        #pragma unroll
        for (int j = 1; j < 5; j++) {
            int idx = (j == 4) ? 1024 : tid + j*256;
            if (v[j] > bv) { bv = v[j]; bi = idx; }
        }
        #pragma unroll
        for (int o = 16; o > 0; o >>= 1) {
            float ov = __shfl_xor_sync(0xffffffffu, bv, o);
            int   oi = __shfl_xor_sync(0xffffffffu, bi, o);
            if (ov > bv || (ov == bv && oi < bi)) { bv = ov; bi = oi; }
        }
        if (lane == 0) { wval[wrp] = bv; widx[wrp] = bi; }
        __syncthreads();
        if (tid < 8) {
            float xv = wval[tid]; int xi = widx[tid];
            #pragma unroll
            for (int o = 4; o > 0; o >>= 1) {
                float ov = __shfl_xor_sync(0x000000ffu, xv, o);
                int   oi = __shfl_xor_sync(0x000000ffu, xi, o);
                if (ov > xv || (ov == xv && oi < xi)) { xv = ov; xi = oi; }
            }
            if (tid == 0) { topk[bhm * 25 + it] = xi; swin = xi; }
        }
        __syncthreads();
        const int win = swin;
        if (win == 1024) { if (tid == 0) v[4] = -INFINITY; }
        else if ((win & 255) == tid) v[win >> 8] = -INFINITY;
    }
}

// ---------------- Mixed attention (expert argmax fused in) ----------------
__global__ void mixed_kernel(const float* __restrict__ qkv, const float* __restrict__ gate,
                             const float* __restrict__ av, const int* __restrict__ topk,
                             float* __restrict__ attn) {
    const int bh = blockIdx.y;
    const int b = bh >> 4, h = bh & 15;
    const int tid = threadIdx.x, lane = tid & 31, w = tid >> 5;
    __shared__ float avs[25][64];
    __shared__ float ws[8][50];
    for (int idx = tid; idx < 1600; idx += 256)
        avs[idx >> 6][idx & 63] = av[(size_t)bh * 1600 + idx];
    __syncthreads();

    const int n = blockIdx.x * 8 + w;
    if (n >= NN) return;

    float gv = (lane < 25) ? gate[((size_t)bh*MM + lane) * NN + n] : -INFINITY;

    float bval = gv; int bidx = (lane < 25) ? lane : 1000;
    #pragma unroll
    for (int o = 16; o > 0; o >>= 1) {
        float ov = __shfl_xor_sync(0xffffffffu, bval, o);
        int   oi = __shfl_xor_sync(0xffffffffu, bidx, o);
        if (ov > bval || (ov == bval && oi < bidx)) { bval = ov; bidx = oi; }
    }
    const int e = bidx;

    const int sel = (lane < 25) ? topk[((size_t)bh*MM + e) * 25 + lane] : 0;

    const float* qrow = qkv + (size_t)(b*NN + n) * QKVLD + h*64;
    const float qa = qrow[lane], qb = qrow[lane + 32];
    const float* kb = qkv + (size_t)b*NN*QKVLD + 1024 + h*64;
    const float* vb = qkv + (size_t)b*NN*QKVLD + 2048 + h*64;

    float L0 = (lane < 25) ? gv * SCALE : -INFINITY;
    float L1 = -INFINITY;

    #pragma unroll
    for (int k = 0; k < 25; k++) {
        int s = __shfl_sync(0xffffffffu, sel, k);
        const float* kr = kb + (size_t)s * QKVLD;
        float part = qa * kr[lane] + qb * kr[lane + 32];
        #pragma unroll
        for (int o = 16; o > 0; o >>= 1) part += __shfl_xor_sync(0xffffffffu, part, o);
        part *= SCALE;
        const int j = 25 + k;
        if (j < 32) { if (lane == j) L0 = part; }
        else        { if (lane == j - 32) L1 = part; }
    }

    float mx = fmaxf(L0, L1);
    #pragma unroll
    for (int o = 16; o > 0; o >>= 1) mx = fmaxf(mx, __shfl_xor_sync(0xffffffffu, mx, o));
    float p0 = __expf(L0 - mx), p1 = __expf(L1 - mx);
    float ssum = p0 + p1;
    #pragma unroll
    for (int o = 16; o > 0; o >>= 1) ssum += __shfl_xor_sync(0xffffffffu, ssum, o);
    const float invs = 1.0f / ssum;

    ws[w][lane] = p0 * invs;
    if (lane < 18) ws[w][32 + lane] = p1 * invs;
    __syncwarp();

    float o0 = 0.0f, o1 = 0.0f;
    #pragma unroll
    for (int m = 0; m < 25; m++) {
        float wt = ws[w][m];
        o0 += wt * avs[m][lane];
        o1 += wt * avs[m][lane + 32];
    }
    #pragma unroll
    for (int k = 0; k < 25; k++) {
        float wt = ws[w][25 + k];
        int s = __shfl_sync(0xffffffffu, sel, k);
        const float* vr = vb + (size_t)s * QKVLD;
        o0 += wt * vr[lane];
        o1 += wt * vr[lane + 32];
    }
    attn[(size_t)(b*NN + n) * CC + h*64 + lane] = o0;
    attn[(size_t)(b*NN + n) * CC + h*64 + lane + 32] = o1;
}

// ---------------- launch ----------------
extern "C" void kernel_launch(void* const* d_in, const int* in_sizes, int n_in,
                              void* d_out, int out_size) {
    const float* x     = (const float*)d_in[0];   // [8,1025,1024]
    const float* Wqkv  = (const float*)d_in[1];   // [1024,3072]
    const float* Wproj = (const float*)d_in[2];   // [1024,1024]
    const float* bproj = (const float*)d_in[3];   // [1024]
    float* out = (float*)d_out;                   // [8,1025,1024]

    float *qkv_p, *router_p, *rlog_p, *gate_p, *av_p, *attn_p;
    int *topk_p;
    cudaGetSymbolAddress((void**)&qkv_p,    g_qkv);
    cudaGetSymbolAddress((void**)&router_p, g_router);
    cudaGetSymbolAddress((void**)&rlog_p,   g_rlog);
    cudaGetSymbolAddress((void**)&gate_p,   g_gate);
    cudaGetSymbolAddress((void**)&av_p,     g_av);
    cudaGetSymbolAddress((void**)&topk_p,   g_topk);
    cudaGetSymbolAddress((void**)&attn_p,   g_attn);

    cudaFuncSetAttribute((const void*)tf32_gemm<false>,
                         cudaFuncAttributeMaxDynamicSharedMemorySize, TF_SMEM);
    cudaFuncSetAttribute((const void*)tf32_gemm<true>,
                         cudaFuncAttributeMaxDynamicSharedMemorySize, TF_SMEM);

    // 1a) q,k = x @ Wqkv[:, 0:2048]  (fp32 — selection-critical)
    sgemm_db<<<dim3(2048/128, (TOT+127)/128), 256>>>(
        x, Wqkv, qkv_p, TOT, QKVLD, CC);

    // 1b) v = x @ Wqkv[:, 2048:3072]  (3xTF32 — smooth path only)
    tf32_gemm<false><<<dim3(1024/128, (TOT+127)/128), 256, TF_SMEM>>>(
        x, Wqkv + 2048, nullptr, qkv_p + 2048, TOT, QKVLD, CC);

    // 2) router tokens
    router_kernel<<<dim3(MM, BB), 256>>>(qkv_p, router_p);

    // 3) r_logits and gate
    rg_kernel<<<dim3((NN+255)/256, BB*HH), 256>>>(qkv_p, router_p, rlog_p, gate_p);

    // 4) fused agent values + register-resident top-25
    agent_topk_kernel<<<BB*HH*MM, 256>>>(rlog_p, qkv_p, av_p, topk_p);

    // 5) mixed attention (expert argmax inlined)
    mixed_kernel<<<dim3((NN+7)/8, BB*HH), 256>>>(qkv_p, gate_p, av_p, topk_p, attn_p);

    // 6) out = attn @ Wproj + bproj (3xTF32 — flip-immune)
    tf32_gemm<true><<<dim3(CC/128, (TOT+127)/128), 256, TF_SMEM>>>(
        attn_p, Wproj, bproj, out, TOT, CC, CC);
}

// round 10
// speedup vs baseline: 1.2738x; 1.0131x over previous
#include <cuda_runtime.h>
#include <cuda_bf16.h>
#include <math.h>
#include <cstdint>

#define BB 8
#define NN 1025
#define CC 1024
#define HH 16
#define MM 25
#define TOT (BB*NN)           // 8200
#define QKVLD 3072
#define SCALE 0.125f

// ---------------- scratch (static device globals) ----------------
__device__ float g_qkv[TOT * QKVLD];
__device__ float g_router[BB * MM * CC];
__device__ float g_rlog[BB * HH * MM * NN];
__device__ float g_gate[BB * HH * MM * NN];
__device__ float g_av[BB * HH * MM * 64];
__device__ int   g_topk[BB * HH * MM * 25];
__device__ float g_attn[TOT * CC];

// ================= PTX helpers =================
__device__ __forceinline__ uint32_t smem_u32(const void* p) {
    return (uint32_t)__cvta_generic_to_shared(p);
}
__device__ __forceinline__ void cp16(uint32_t saddr, const void* g) {
    asm volatile("cp.async.cg.shared.global [%0], [%1], 16;" :: "r"(saddr), "l"(g));
}
__device__ __forceinline__ void cp16z(uint32_t saddr, const void* g, bool ok) {
    int sz = ok ? 16 : 0;
    asm volatile("cp.async.cg.shared.global [%0], [%1], 16, %2;"
                 :: "r"(saddr), "l"(g), "r"(sz));
}
__device__ __forceinline__ uint32_t f2tf(float v) {
    uint32_t r; asm("cvt.rna.tf32.f32 %0, %1;" : "=r"(r) : "f"(v)); return r;
}
__device__ __forceinline__ void split_tf(float v, uint32_t& hi, uint32_t& lo) {
    hi = f2tf(v);
    lo = f2tf(v - __uint_as_float(hi));
}
__device__ __forceinline__ void mma_tf32(float* c, const uint32_t* a, uint32_t b0, uint32_t b1) {
    asm volatile("mma.sync.aligned.m16n8k8.row.col.f32.tf32.tf32.f32 "
        "{%0,%1,%2,%3}, {%4,%5,%6,%7}, {%8,%9}, {%0,%1,%2,%3};"
        : "+f"(c[0]), "+f"(c[1]), "+f"(c[2]), "+f"(c[3])
        : "r"(a[0]), "r"(a[1]), "r"(a[2]), "r"(a[3]), "r"(b0), "r"(b1));
}

// ================= FP32 GEMM (q,k — selection-critical): 128x128x8 double-buffered =================
__global__ __launch_bounds__(256) void sgemm_db(
    const float* __restrict__ A, const float* __restrict__ W,
    float* __restrict__ C, int M, int N, int K)
{
    __shared__ float As[2][8][128];
    __shared__ float Bs[2][8][128];
    const int tid = threadIdx.x;
    const int tx = tid & 15, ty = tid >> 4;
    const int brow = blockIdx.y * 128, bcol = blockIdx.x * 128;

    const int arow = tid >> 1, acol = (tid & 1) * 4;
    const int bkrow = tid >> 5, bncol = (tid & 31) * 4;

    const bool aok = (brow + arow) < M;
    const float* Ap = A + (size_t)(brow + arow) * K + acol;
    const float* Bp = W + (size_t)bkrow * N + bcol + bncol;

    float acc[8][8];
    #pragma unroll
    for (int i = 0; i < 8; i++)
        #pragma unroll
        for (int j = 0; j < 8; j++) acc[i][j] = 0.0f;

    float4 av = aok ? *(const float4*)Ap : make_float4(0.f,0.f,0.f,0.f);
    float4 bv = *(const float4*)Bp;
    As[0][acol+0][arow] = av.x; As[0][acol+1][arow] = av.y;
    As[0][acol+2][arow] = av.z; As[0][acol+3][arow] = av.w;
    *(float4*)&Bs[0][bkrow][bncol] = bv;
    __syncthreads();

    const int S = K >> 3;
    #pragma unroll 1
    for (int s = 0; s < S; s++) {
        const int cur = s & 1;
        if (s + 1 < S) {
            av = aok ? *(const float4*)(Ap + (s + 1) * 8) : make_float4(0.f,0.f,0.f,0.f);
            bv = *(const float4*)(Bp + (size_t)(s + 1) * 8 * N);
        }
        #pragma unroll
        for (int k = 0; k < 8; k++) {
            float4 a0 = ((const float4*)As[cur][k])[ty];
            float4 a1 = ((const float4*)As[cur][k])[16 + ty];
            float4 b0 = ((const float4*)Bs[cur][k])[tx];
            float4 b1 = ((const float4*)Bs[cur][k])[16 + tx];
            float a[8] = {a0.x,a0.y,a0.z,a0.w,a1.x,a1.y,a1.z,a1.w};
            float b[8] = {b0.x,b0.y,b0.z,b0.w,b1.x,b1.y,b1.z,b1.w};
            #pragma unroll
            for (int i = 0; i < 8; i++)
                #pragma unroll
                for (int j = 0; j < 8; j++)
                    acc[i][j] += a[i] * b[j];
        }
        if (s + 1 < S) {
            const int nxt = cur ^ 1;
            As[nxt][acol+0][arow] = av.x; As[nxt][acol+1][arow] = av.y;
            As[nxt][acol+2][arow] = av.z; As[nxt][acol+3][arow] = av.w;
            *(float4*)&Bs[nxt][bkrow][bncol] = bv;
        }
        __syncthreads();
    }

    #pragma unroll
    for (int i = 0; i < 8; i++) {
        int r = brow + (i < 4 ? ty*4 + i : 64 + ty*4 + (i-4));
        if (r >= M) continue;
        int c0 = bcol + tx*4;
        int c1 = bcol + 64 + tx*4;
        float4 o0, o1;
        o0.x = acc[i][0]; o0.y = acc[i][1]; o0.z = acc[i][2]; o0.w = acc[i][3];
        o1.x = acc[i][4]; o1.y = acc[i][5]; o1.z = acc[i][6]; o1.w = acc[i][7];
        *(float4*)&C[(size_t)r * N + c0] = o0;
        *(float4*)&C[(size_t)r * N + c1] = o1;
    }
}

// ================= 3xTF32 GEMM (smooth paths): 2-stage, 2 CTAs/SM =================
#define SA_F (128*36)
#define SW_F (32*136)
#define STG_F (SA_F + SW_F)          // 8960 floats = 35840 B per stage
#define TF_SMEM (2 * STG_F * 4)      // 71680 B

template<bool BIAS>
__global__ __launch_bounds__(256, 2) void tf32_gemm(
    const float* __restrict__ A, const float* __restrict__ W,
    const float* __restrict__ bias, float* __restrict__ C,
    int Mvalid, int N, int K)
{
    extern __shared__ float sm[];
    const int tid = threadIdx.x, lane = tid & 31, wid = tid >> 5;
    const int gid = lane >> 2, tig = lane & 3;
    const int wm = wid >> 2, wn = wid & 3;
    const int m0 = blockIdx.y * 128, n0 = blockIdx.x * 128;
    const uint32_t sb = smem_u32(sm);

    float acc[4][4][4];
    #pragma unroll
    for (int a = 0; a < 4; a++)
        #pragma unroll
        for (int b = 0; b < 4; b++)
            #pragma unroll
            for (int c = 0; c < 4; c++) acc[a][b][c] = 0.0f;

    const int S = K >> 5;

    auto load_stage = [&](int s) {
        const int k0 = s * 32;
        const uint32_t st = sb + (uint32_t)((s & 1) * STG_F * 4);
        #pragma unroll
        for (int i = 0; i < 4; i++) {
            int idx = i * 256 + tid;
            int ar = idx >> 3, ac = (idx & 7) * 4;
            cp16z(st + (uint32_t)(ar*36 + ac)*4, A + (size_t)(m0+ar)*K + k0 + ac,
                  (m0 + ar) < Mvalid);
        }
        #pragma unroll
        for (int i = 0; i < 4; i++) {
            int idx = i * 256 + tid;
            int wr = idx >> 5, wc = (idx & 31) * 4;
            cp16(st + (uint32_t)(SA_F + wr*136 + wc)*4, W + (size_t)(k0+wr)*N + n0 + wc);
        }
        asm volatile("cp.async.commit_group;" ::: "memory");
    };

    load_stage(0);
    load_stage(1);

    #pragma unroll 1
    for (int s = 0; s < S; s++) {
        if (s + 1 < S) {
            asm volatile("cp.async.wait_group 1;" ::: "memory");
        } else {
            asm volatile("cp.async.wait_group 0;" ::: "memory");
        }
        __syncthreads();

        const float* sA = sm + (s & 1) * STG_F;
        const float* sW = sA + SA_F;

        #pragma unroll
        for (int ks = 0; ks < 4; ks++) {
            uint32_t ahi[4][4], alo[4][4];
            #pragma unroll
            for (int mi = 0; mi < 4; mi++) {
                const int r0 = wm*64 + mi*16 + gid;
                const int c  = ks*8 + tig;
                split_tf(sA[r0*36 + c],       ahi[mi][0], alo[mi][0]);
                split_tf(sA[(r0+8)*36 + c],   ahi[mi][1], alo[mi][1]);
                split_tf(sA[r0*36 + c + 4],   ahi[mi][2], alo[mi][2]);
                split_tf(sA[(r0+8)*36 + c+4], ahi[mi][3], alo[mi][3]);
            }
            #pragma unroll
            for (int nj = 0; nj < 4; nj++) {
                const int kr = ks*8 + tig;
                const int bn = wn*32 + nj*8 + gid;
                uint32_t bh0, bl0, bh1, bl1;
                split_tf(sW[kr*136 + bn],     bh0, bl0);
                split_tf(sW[(kr+4)*136 + bn], bh1, bl1);
                #pragma unroll
                for (int mi = 0; mi < 4; mi++) {
                    mma_tf32(acc[mi][nj], ahi[mi], bh0, bh1);
                    mma_tf32(acc[mi][nj], ahi[mi], bl0, bl1);
                    mma_tf32(acc[mi][nj], alo[mi], bh0, bh1);
                }
            }
        }
        __syncthreads();
        if (s + 2 < S) load_stage(s + 2);
    }

    #pragma unroll
    for (int mi = 0; mi < 4; mi++) {
        const int r0 = m0 + wm*64 + mi*16 + gid;
        #pragma unroll
        for (int nj = 0; nj < 4; nj++) {
            const int col = n0 + wn*32 + nj*8 + tig*2;
            float2 v0 = make_float2(acc[mi][nj][0], acc[mi][nj][1]);
            float2 v1 = make_float2(acc[mi][nj][2], acc[mi][nj][3]);
            if (BIAS) {
                float bx = bias[col], by = bias[col+1];
                v0.x += bx; v0.y += by; v1.x += bx; v1.y += by;
            }
            if (r0 < Mvalid)     *(float2*)&C[(size_t)r0 * N + col] = v0;
            if (r0 + 8 < Mvalid) *(float2*)&C[(size_t)(r0+8) * N + col] = v1;
        }
    }
}

// ---------------- Router: adaptive avg pool of q (32x32 -> 5x5) ----------------
__global__ void router_kernel(const float* __restrict__ qkv, float* __restrict__ router) {
    const int m = blockIdx.x, b = blockIdx.y;
    const int i = m / 5, j = m % 5;
    const int s[5] = {0, 6, 12, 19, 25};
    const int e[5] = {7, 13, 20, 26, 32};
    const float inv = 1.0f / (float)((e[i]-s[i]) * (e[j]-s[j]));
    for (int c = threadIdx.x; c < CC; c += blockDim.x) {
        float acc = 0.0f;
        for (int gh = s[i]; gh < e[i]; gh++)
            for (int gw = s[j]; gw < e[j]; gw++)
                acc += qkv[(size_t)(b*NN + gh*32 + gw) * QKVLD + c];
        router[(size_t)(b*MM + m) * CC + c] = acc * inv;
    }
}

// ---------------- r_logits = r@k^T, gate = r@q^T (m-chunked for occupancy) ----------------
#define MCHUNK 13
__global__ __launch_bounds__(256) void rg_kernel(
    const float* __restrict__ qkv, const float* __restrict__ router,
    float* __restrict__ rlog, float* __restrict__ gate) {
    const int bh = blockIdx.y;
    const int b = bh >> 4, h = bh & 15;
    const int t0 = blockIdx.x * 256;
    const int mbase = blockIdx.z * MCHUNK;            // 0 or 13
    const int mcnt = (blockIdx.z == 0) ? MCHUNK : (MM - MCHUNK);   // 13 or 12
    const int tid = threadIdx.x;
    __shared__ float rsm[MCHUNK][64];
    __shared__ float ks[256][17];
    __shared__ float qs[256][17];

    for (int idx = tid; idx < mcnt * 64; idx += 256)
        rsm[idx >> 6][idx & 63] =
            router[(size_t)(b*MM + mbase + (idx >> 6)) * CC + h*64 + (idx & 63)];

    float acc_k[MCHUNK], acc_q[MCHUNK];
    #pragma unroll
    for (int m = 0; m < MCHUNK; m++) { acc_k[m] = 0.0f; acc_q[m] = 0.0f; }

    const int n = t0 + tid;
    for (int dc = 0; dc < 64; dc += 16) {
        __syncthreads();
        for (int idx = tid; idx < 256*16; idx += 256) {
            int tok = idx >> 4, dd = idx & 15;
            int gn = t0 + tok;
            float kv = 0.0f, qv = 0.0f;
            if (gn < NN) {
                const float* base = qkv + (size_t)(b*NN + gn) * QKVLD + h*64 + dc + dd;
                qv = base[0];
                kv = base[1024];
            }
            ks[tok][dd] = kv; qs[tok][dd] = qv;
        }
        __syncthreads();
        #pragma unroll
        for (int d = 0; d < 16; d++) {
            float kd = ks[tid][d], qd = qs[tid][d];
            #pragma unroll
            for (int m = 0; m < MCHUNK; m++) {
                float r = rsm[m][dc + d];
                acc_k[m] += r * kd;
                acc_q[m] += r * qd;
            }
        }
    }
    if (n < NN) {
        #pragma unroll
        for (int m = 0; m < MCHUNK; m++) {
            if (m < mcnt) {
                rlog[((size_t)bh*MM + mbase + m) * NN + n] = acc_k[m];
                gate[((size_t)bh*MM + mbase + m) * NN + n] = acc_q[m];
            }
        }
    }
}

// ---------------- Fused agent (softmax @ V) + register-resident top-25 ----------------
__global__ __launch_bounds__(256) void agent_topk_kernel(
    const float* __restrict__ rlog, const float* __restrict__ qkv,
    float* __restrict__ av, int* __restrict__ topk) {
    const int bhm = blockIdx.x;
    const int bh = bhm / 25;
    const int b = bh >> 4, h = bh & 15;
    const float* row = rlog + (size_t)bhm * NN;
    __shared__ float p[NN];
    __shared__ float red[256];
    __shared__ float part[4][64];
    __shared__ float wval[8];
    __shared__ int   widx[8];
    __shared__ int   swin;
    const int tid = threadIdx.x;  // 256
    const int lane = tid & 31, wrp = tid >> 5;

    float v[5];
    #pragma unroll
    for (int j = 0; j < 4; j++) v[j] = row[tid + j*256];
    v[4] = (tid == 0) ? row[1024] : -INFINITY;

    float mx = v[0];
    #pragma unroll
    for (int j = 1; j < 5; j++) mx = fmaxf(mx, v[j]);
    red[tid] = mx; __syncthreads();
    for (int s = 128; s > 0; s >>= 1) {
        if (tid < s) red[tid] = fmaxf(red[tid], red[tid + s]);
        __syncthreads();
    }
    mx = red[0];
    __syncthreads();

    float sum = 0.0f;
    #pragma unroll
    for (int j = 0; j < 4; j++) {
        float e = __expf((v[j] - mx) * SCALE);
        p[tid + j*256] = e; sum += e;
    }
    if (tid == 0) {
        float e = __expf((v[4] - mx) * SCALE);
        p[1024] = e; sum += e;
    }
    red[tid] = sum; __syncthreads();
    for (int s = 128; s > 0; s >>= 1) {
        if (tid < s) red[tid] += red[tid + s];
        __syncthreads();
    }
    const float inv = 1.0f / red[0];
    __syncthreads();

    const int g = tid >> 6, d = tid & 63;
    const float* vb = qkv + (size_t)b*NN*QKVLD + 2048 + h*64 + d;
    float acc = 0.0f;
    #pragma unroll 8
    for (int n = g; n < NN; n += 4) acc += p[n] * vb[(size_t)n * QKVLD];
    part[g][d] = acc;
    __syncthreads();
    if (tid < 64)
        av[(size_t)bhm * 64 + tid] =
            (part[0][tid] + part[1][tid] + part[2][tid] + part[3][tid]) * inv;

    for (int it = 0; it < 25; it++) {
        float bv = v[0]; int bi = tid;
        #pragma unroll
        for (int j = 1; j < 5; j++) {
            int idx = (j == 4) ? 1024 : tid + j*256;
            if (v[j] > bv) { bv = v[j]; bi = idx; }
        }
        #pragma unroll
        for (int o = 16; o > 0; o >>= 1) {
            float ov = __shfl_xor_sync(0xffffffffu, bv, o);
            int   oi = __shfl_xor_sync(0xffffffffu, bi, o);
            if (ov > bv || (ov == bv && oi < bi)) { bv = ov; bi = oi; }
        }
        if (lane == 0) { wval[wrp] = bv; widx[wrp] = bi; }
        __syncthreads();
        if (tid < 8) {
            float xv = wval[tid]; int xi = widx[tid];
            #pragma unroll
            for (int o = 4; o > 0; o >>= 1) {
                float ov = __shfl_xor_sync(0x000000ffu, xv, o);
                int   oi = __shfl_xor_sync(0x000000ffu, xi, o);
                if (ov > xv || (ov == xv && oi < xi)) { xv = ov; xi = oi; }
            }
            if (tid == 0) { topk[bhm * 25 + it] = xi; swin = xi; }
        }
        __syncthreads();
        const int win = swin;
        if (win == 1024) { if (tid == 0) v[4] = -INFINITY; }
        else if ((win & 255) == tid) v[win >> 8] = -INFINITY;
    }
}

// ---------------- Mixed attention (expert argmax fused in) ----------------
__global__ void mixed_kernel(const float* __restrict__ qkv, const float* __restrict__ gate,
                             const float* __restrict__ av, const int* __restrict__ topk,
                             float* __restrict__ attn) {
    const int bh = blockIdx.y;
    const int b = bh >> 4, h = bh & 15;
    const int tid = threadIdx.x, lane = tid & 31, w = tid >> 5;
    __shared__ float avs[25][64];
    __shared__ float ws[8][50];
    for (int idx = tid; idx < 1600; idx += 256)
        avs[idx >> 6][idx & 63] = av[(size_t)bh * 1600 + idx];
    __syncthreads();

    const int n = blockIdx.x * 8 + w;
    if (n >= NN) return;

    float gv = (lane < 25) ? gate[((size_t)bh*MM + lane) * NN + n] : -INFINITY;

    float bval = gv; int bidx = (lane < 25) ? lane : 1000;
    #pragma unroll
    for (int o = 16; o > 0; o >>= 1) {
        float ov = __shfl_xor_sync(0xffffffffu, bval, o);
        int   oi = __shfl_xor_sync(0xffffffffu, bidx, o);
        if (ov > bval || (ov == bval && oi < bidx)) { bval = ov; bidx = oi; }
    }
    const int e = bidx;

    const int sel = (lane < 25) ? topk[((size_t)bh*MM + e) * 25 + lane] : 0;

    const float* qrow = qkv + (size_t)(b*NN + n) * QKVLD + h*64;
    const float qa = qrow[lane], qb = qrow[lane + 32];
    const float* kb = qkv + (size_t)b*NN*QKVLD + 1024 + h*64;
    const float* vb = qkv + (size_t)b*NN*QKVLD + 2048 + h*64;

    float L0 = (lane < 25) ? gv * SCALE : -INFINITY;
    float L1 = -INFINITY;

    #pragma unroll
    for (int k = 0; k < 25; k++) {
        int s = __shfl_sync(0xffffffffu, sel, k);
        const float* kr = kb + (size_t)s * QKVLD;
        float part = qa * kr[lane] + qb * kr[lane + 32];
        #pragma unroll
        for (int o = 16; o > 0; o >>= 1) part += __shfl_xor_sync(0xffffffffu, part, o);
        part *= SCALE;
        const int j = 25 + k;
        if (j < 32) { if (lane == j) L0 = part; }
        else        { if (lane == j - 32) L1 = part; }
    }

    float mx = fmaxf(L0, L1);
    #pragma unroll
    for (int o = 16; o > 0; o >>= 1) mx = fmaxf(mx, __shfl_xor_sync(0xffffffffu, mx, o));
    float p0 = __expf(L0 - mx), p1 = __expf(L1 - mx);
    float ssum = p0 + p1;
    #pragma unroll
    for (int o = 16; o > 0; o >>= 1) ssum += __shfl_xor_sync(0xffffffffu, ssum, o);
    const float invs = 1.0f / ssum;

    ws[w][lane] = p0 * invs;
    if (lane < 18) ws[w][32 + lane] = p1 * invs;
    __syncwarp();

    float o0 = 0.0f, o1 = 0.0f;
    #pragma unroll
    for (int m = 0; m < 25; m++) {
        float wt = ws[w][m];
        o0 += wt * avs[m][lane];
        o1 += wt * avs[m][lane + 32];
    }
    #pragma unroll
    for (int k = 0; k < 25; k++) {
        float wt = ws[w][25 + k];
        int s = __shfl_sync(0xffffffffu, sel, k);
        const float* vr = vb + (size_t)s * QKVLD;
        o0 += wt * vr[lane];
        o1 += wt * vr[lane + 32];
    }
    attn[(size_t)(b*NN + n) * CC + h*64 + lane] = o0;
    attn[(size_t)(b*NN + n) * CC + h*64 + lane + 32] = o1;
}

// ---------------- launch ----------------
extern "C" void kernel_launch(void* const* d_in, const int* in_sizes, int n_in,
                              void* d_out, int out_size) {
    const float* x     = (const float*)d_in[0];   // [8,1025,1024]
    const float* Wqkv  = (const float*)d_in[1];   // [1024,3072]
    const float* Wproj = (const float*)d_in[2];   // [1024,1024]
    const float* bproj = (const float*)d_in[3];   // [1024]
    float* out = (float*)d_out;                   // [8,1025,1024]

    float *qkv_p, *router_p, *rlog_p, *gate_p, *av_p, *attn_p;
    int *topk_p;
    cudaGetSymbolAddress((void**)&qkv_p,    g_qkv);
    cudaGetSymbolAddress((void**)&router_p, g_router);
    cudaGetSymbolAddress((void**)&rlog_p,   g_rlog);
    cudaGetSymbolAddress((void**)&gate_p,   g_gate);
    cudaGetSymbolAddress((void**)&av_p,     g_av);
    cudaGetSymbolAddress((void**)&topk_p,   g_topk);
    cudaGetSymbolAddress((void**)&attn_p,   g_attn);

    cudaFuncSetAttribute((const void*)tf32_gemm<false>,
                         cudaFuncAttributeMaxDynamicSharedMemorySize, TF_SMEM);
    cudaFuncSetAttribute((const void*)tf32_gemm<true>,
                         cudaFuncAttributeMaxDynamicSharedMemorySize, TF_SMEM);

    // 1a) q,k = x @ Wqkv[:, 0:2048]  (fp32 — selection-critical)
    sgemm_db<<<dim3(2048/128, (TOT+127)/128), 256>>>(
        x, Wqkv, qkv_p, TOT, QKVLD, CC);

    // 1b) v = x @ Wqkv[:, 2048:3072]  (3xTF32 — smooth path only)
    tf32_gemm<false><<<dim3(1024/128, (TOT+127)/128), 256, TF_SMEM>>>(
        x, Wqkv + 2048, nullptr, qkv_p + 2048, TOT, QKVLD, CC);

    // 2) router tokens
    router_kernel<<<dim3(MM, BB), 256>>>(qkv_p, router_p);

    // 3) r_logits and gate (m-chunked)
    rg_kernel<<<dim3((NN+255)/256, BB*HH, 2), 256>>>(qkv_p, router_p, rlog_p, gate_p);

    // 4) fused agent values + register-resident top-25
    agent_topk_kernel<<<BB*HH*MM, 256>>>(rlog_p, qkv_p, av_p, topk_p);

    // 5) mixed attention (expert argmax inlined)
    mixed_kernel<<<dim3((NN+7)/8, BB*HH), 256>>>(qkv_p, gate_p, av_p, topk_p, attn_p);

    // 6) out = attn @ Wproj + bproj (3xTF32 — flip-immune)
    tf32_gemm<true><<<dim3(CC/128, (TOT+127)/128), 256, TF_SMEM>>>(
        attn_p, Wproj, bproj, out, TOT, CC, CC);
}